// round 13
// baseline (speedup 1.0000x reference)
#include <cuda_runtime.h>
#include <cstdint>

// Problem constants
#define NB   4
#define SEQ  1024
#define NH   16
#define DH   64
#define DM   1024
#define MROWS (NB * SEQ)

// Pre-split tf32 hi/lo copies of the GEMM inputs.
__device__ float g_xh[MROWS * DM], g_xl[MROWS * DM];
__device__ float g_wh[3 * DM * DM], g_wl[3 * DM * DM];

// Pre-split tf32 hi/lo Q/K ([B,H,S,DH], paired d-permutation) and V hi only
// ([B,H,DH,S] transposed, paired s-permutation).
__device__ float g_qh[NB * NH * SEQ * DH];
__device__ float g_ql[NB * NH * SEQ * DH];
__device__ float g_kh[NB * NH * SEQ * DH];
__device__ float g_kl[NB * NH * SEQ * DH];
__device__ float g_vh[NB * NH * SEQ * DH];

__device__ __forceinline__ int perm8(int x) { return ((x & 3) << 1) | ((x >> 2) & 1); }

__device__ __forceinline__ float to_tf32(float x) {
    unsigned u;
    asm("cvt.rna.tf32.f32 %0, %1;" : "=r"(u) : "f"(x));
    return __uint_as_float(u);
}
__device__ __forceinline__ void split_tf32(float x, float& hi, float& lo) {
    hi = to_tf32(x);
    lo = to_tf32(x - hi);
}
__device__ __forceinline__ void mma_tf32(float* c, const unsigned* a, const unsigned* b) {
    asm volatile(
        "mma.sync.aligned.m16n8k8.row.col.f32.tf32.tf32.f32 "
        "{%0,%1,%2,%3},{%4,%5,%6,%7},{%8,%9},{%0,%1,%2,%3};"
        : "+f"(c[0]), "+f"(c[1]), "+f"(c[2]), "+f"(c[3])
        : "r"(a[0]), "r"(a[1]), "r"(a[2]), "r"(a[3]), "r"(b[0]), "r"(b[1]));
}
__device__ __forceinline__ float warpMax(float v) {
#pragma unroll
    for (int o = 16; o > 0; o >>= 1) v = fmaxf(v, __shfl_xor_sync(0xffffffffu, v, o));
    return v;
}
__device__ __forceinline__ float warpSum(float v) {
#pragma unroll
    for (int o = 16; o > 0; o >>= 1) v += __shfl_xor_sync(0xffffffffu, v, o);
    return v;
}

#define CP_COMMIT() asm volatile("cp.async.commit_group;")
#define CP_WAIT(N)  asm volatile("cp.async.wait_group %0;" :: "n"(N))

__device__ __forceinline__ void cp16(float* dst, const float* src) {
    uint32_t a = (uint32_t)__cvta_generic_to_shared(dst);
    asm volatile("cp.async.cg.shared.global [%0], [%1], 16;" :: "r"(a), "l"(src));
}

// ---------------------------------------------------------------------------
// Pre-split X, Wq, Wk, Wv into tf32 hi/lo device arrays. Memory-bound.
// ---------------------------------------------------------------------------
__global__ __launch_bounds__(256) void presplit_kernel(
    const float* __restrict__ X, const float* __restrict__ Wq,
    const float* __restrict__ Wk, const float* __restrict__ Wv) {
    const size_t NX = (size_t)MROWS * DM / 4;
    const size_t NW = (size_t)DM * DM / 4;
    size_t i = (size_t)blockIdx.x * 256 + threadIdx.x;
    const float4* src;
    float4 *dh, *dl;
    size_t j;
    if (i < NX)               { src = (const float4*)X;  dh = (float4*)g_xh;      dl = (float4*)g_xl;      j = i; }
    else if (i < NX + NW)     { src = (const float4*)Wq; dh = (float4*)g_wh;      dl = (float4*)g_wl;      j = i - NX; }
    else if (i < NX + 2 * NW) { src = (const float4*)Wk; dh = (float4*)g_wh + NW; dl = (float4*)g_wl + NW; j = i - NX - NW; }
    else                      { src = (const float4*)Wv; dh = (float4*)g_wh + 2 * NW; dl = (float4*)g_wl + 2 * NW; j = i - NX - 2 * NW; }
    float4 v = src[j];
    float4 hv, lv;
    split_tf32(v.x, hv.x, lv.x); split_tf32(v.y, hv.y, lv.y);
    split_tf32(v.z, hv.z, lv.z); split_tf32(v.w, hv.w, lv.w);
    dh[j] = hv;
    dl[j] = lv;
}

// ---------------------------------------------------------------------------
// QKV projection, 3xTF32 (R12-proven). 256 threads, 8 warps (64x32 warp
// tiles), CTA tile 128x128, k-stage 16 double-buffered, 2 CTAs/SM.
// ---------------------------------------------------------------------------
constexpr int PKS  = 16;
constexpr int PXS  = 20;
constexpr int PWS  = 136;
constexpr int XSTG = 128 * PXS;
constexpr int WSTG = PKS * PWS;
constexpr int STG  = 2 * XSTG + 2 * WSTG;
constexpr int PROJ_SMEM_FLOATS = 2 * STG;

__device__ __forceinline__ void proj_stage(float* s, const float* xh, const float* xl,
                                           const float* wh, const float* wl,
                                           int m0, int n0, int k0, int tid) {
    float* Xh = s;
    float* Xl = s + XSTG;
    float* Wh = s + 2 * XSTG;
    float* Wl = s + 2 * XSTG + WSTG;
#pragma unroll
    for (int it = 0; it < 2; ++it) {
        const int idx = tid + 256 * it;
        const int r = idx >> 2, c = (idx & 3) << 2;
        const size_t go = (size_t)(m0 + r) * DM + k0 + c;
        cp16(Xh + r * PXS + c, xh + go);
        cp16(Xl + r * PXS + c, xl + go);
    }
#pragma unroll
    for (int it = 0; it < 2; ++it) {
        const int idx = tid + 256 * it;
        const int r = idx >> 5, c = (idx & 31) << 2;
        const size_t go = (size_t)(k0 + r) * DM + n0 + c;
        cp16(Wh + r * PWS + c, wh + go);
        cp16(Wl + r * PWS + c, wl + go);
    }
}

__global__ __launch_bounds__(256, 2) void qkv_proj_tc(
    const float* __restrict__ bq, const float* __restrict__ bk,
    const float* __restrict__ bv) {
    extern __shared__ float psm[];

    const int z = blockIdx.z;
    const float* wh = g_wh + (size_t)z * DM * DM;
    const float* wl = g_wl + (size_t)z * DM * DM;
    const float* bias = (z == 0) ? bq : (z == 1) ? bk : bv;
    float* outh = (z == 0) ? g_qh : (z == 1) ? g_kh : g_vh;
    float* outl = (z == 0) ? g_ql : g_kl;
    const bool isV = (z == 2);

    const int tid = threadIdx.x;
    const int warp = tid >> 5, lane = tid & 31;
    const int g = lane >> 2, t = lane & 3;
    const int wm = (warp >> 2) * 64, wn = (warp & 3) * 32;
    const int m0 = blockIdx.y * 128, n0 = blockIdx.x * 128;

    float acc[4][4][4] = {};

    proj_stage(psm, g_xh, g_xl, wh, wl, m0, n0, 0, tid);
    CP_COMMIT();

    for (int kb = 0; kb < DM / PKS; ++kb) {
        CP_WAIT(0);
        __syncthreads();
        if (kb + 1 < DM / PKS) {
            proj_stage(psm + ((kb + 1) & 1) * STG, g_xh, g_xl, wh, wl,
                       m0, n0, (kb + 1) * PKS, tid);
            CP_COMMIT();
        }
        const float* Xh = psm + (kb & 1) * STG;
        const float* Xl = Xh + XSTG;
        const float* Wh = Xh + 2 * XSTG;
        const float* Wl = Xh + 2 * XSTG + WSTG;

#pragma unroll
        for (int ks = 0; ks < 2; ++ks) {
            unsigned ah[4][4], al[4][4], bh[4][2], bl[4][2];
#pragma unroll
            for (int i = 0; i < 4; ++i) {
                const int off = (wm + 16 * i + g) * PXS + 8 * ks + t;
                ah[i][0] = __float_as_uint(Xh[off]);
                ah[i][1] = __float_as_uint(Xh[off + 8 * PXS]);
                ah[i][2] = __float_as_uint(Xh[off + 4]);
                ah[i][3] = __float_as_uint(Xh[off + 8 * PXS + 4]);
                al[i][0] = __float_as_uint(Xl[off]);
                al[i][1] = __float_as_uint(Xl[off + 8 * PXS]);
                al[i][2] = __float_as_uint(Xl[off + 4]);
                al[i][3] = __float_as_uint(Xl[off + 8 * PXS + 4]);
            }
#pragma unroll
            for (int j = 0; j < 4; ++j) {
                const int off = (8 * ks + t) * PWS + wn + 8 * j + g;
                bh[j][0] = __float_as_uint(Wh[off]);
                bh[j][1] = __float_as_uint(Wh[off + 4 * PWS]);
                bl[j][0] = __float_as_uint(Wl[off]);
                bl[j][1] = __float_as_uint(Wl[off + 4 * PWS]);
            }
#pragma unroll
            for (int i = 0; i < 4; ++i)
#pragma unroll
                for (int j = 0; j < 4; ++j)
                    mma_tf32(acc[i][j], ah[i], bh[j]);
#pragma unroll
            for (int i = 0; i < 4; ++i)
#pragma unroll
                for (int j = 0; j < 4; ++j)
                    mma_tf32(acc[i][j], al[i], bh[j]);
#pragma unroll
            for (int i = 0; i < 4; ++i)
#pragma unroll
                for (int j = 0; j < 4; ++j)
                    mma_tf32(acc[i][j], ah[i], bl[j]);
        }
    }

    // epilogue: + bias, split, scatter into permuted layouts
#pragma unroll
    for (int j = 0; j < 4; ++j) {
        const int n = n0 + wn + 8 * j + 2 * t;
        const float b0v = bias[n], b1v = bias[n + 1];
        const int h = n >> 6, hd = n & 63;
        const int pd = (hd & ~7) | perm8(hd & 7);
#pragma unroll
        for (int i = 0; i < 4; ++i) {
            const int m = m0 + wm + 16 * i + g;
            const int bI = m >> 10, s = m & 1023;
            const int m2 = m + 8;
            const int bI2 = m2 >> 10, s2 = m2 & 1023;
            const float v0 = acc[i][j][0] + b0v;
            const float v1 = acc[i][j][1] + b1v;
            const float v2 = acc[i][j][2] + b0v;
            const float v3 = acc[i][j][3] + b1v;
            if (!isV) {
                float h0, l0, h1, l1, h2, l2, h3, l3;
                split_tf32(v0, h0, l0);
                split_tf32(v1, h1, l1);
                split_tf32(v2, h2, l2);
                split_tf32(v3, h3, l3);
                const size_t b1o = ((size_t)((bI * NH + h) * SEQ + s)) * DH;
                outh[b1o + pd] = h0;  outh[b1o + pd + 2] = h1;
                outl[b1o + pd] = l0;  outl[b1o + pd + 2] = l1;
                const size_t b2o = ((size_t)((bI2 * NH + h) * SEQ + s2)) * DH;
                outh[b2o + pd] = h2;  outh[b2o + pd + 2] = h3;
                outl[b2o + pd] = l2;  outl[b2o + pd + 2] = l3;
            } else {
                const int ps1 = (s & ~7) | perm8(s & 7);
                const int ps2 = (s2 & ~7) | perm8(s2 & 7);
                const size_t r0 = ((size_t)((bI * NH + h) * DH + hd)) * SEQ;
                const size_t r1 = ((size_t)((bI * NH + h) * DH + hd + 1)) * SEQ;
                outh[r0 + ps1] = to_tf32(v0);  outh[r1 + ps1] = to_tf32(v1);
                const size_t r0b = ((size_t)((bI2 * NH + h) * DH + hd)) * SEQ;
                const size_t r1b = ((size_t)((bI2 * NH + h) * DH + hd + 1)) * SEQ;
                outh[r0b + ps2] = to_tf32(v2);  outh[r1b + ps2] = to_tf32(v3);
            }
        }
    }
}

// ---------------------------------------------------------------------------
// Attention, 512 threads. NO K/V smem staging: all Q/K/V fragments loaded
// directly from GMEM (pre-split, pre-permuted, perfectly coalesced LDG.64,
// depth-2 software pipeline). Only the score buffer lives in smem.
// Exactly 2 barriers (around phase 2). Math identical to R12.
// ---------------------------------------------------------------------------
constexpr int TQ  = 32;
constexpr int CK  = 64;
constexpr int NCH = SEQ / CK;     // 16
constexpr int NT  = 512;
constexpr int SCP = 1032;
constexpr int ATTN_SMEM_FLOATS = TQ * SCP;   // 132 KB
constexpr float SCALE = 0.125f;

__global__ __launch_bounds__(NT, 1) void attn_tc(const float* __restrict__ mask,
                                                 float* __restrict__ out) {
    extern __shared__ float sm[];
    float* sc = sm;                    // [TQ][SCP]

    const int tid = threadIdx.x;
    const int b = blockIdx.z, h = blockIdx.y;
    const int q0 = blockIdx.x * TQ;
    const int bh_i = b * NH + h;
    const float* Qh = g_qh + ((size_t)bh_i * SEQ + q0) * DH;
    const float* Ql = g_ql + ((size_t)bh_i * SEQ + q0) * DH;
    const float* Kh = g_kh + (size_t)bh_i * SEQ * DH;
    const float* Kl = g_kl + (size_t)bh_i * SEQ * DH;
    const float* Vh = g_vh + (size_t)bh_i * DH * SEQ;
    const float* mrow = mask + b * SEQ;

    const int warp = tid >> 5, lane = tid & 31;
    const int g = lane >> 2, t = lane & 3;
    const int wq = warp >> 3;
    const int wk = warp & 7;

    // Q fragments direct from GMEM (held in registers for all of phase 1)
    unsigned qah[8][4], qal[8][4];
    {
        const float* qh0 = Qh + (16 * wq + g) * DH + 2 * t;
        const float* ql0 = Ql + (16 * wq + g) * DH + 2 * t;
#pragma unroll
        for (int ks = 0; ks < 8; ++ks) {
            float2 f0 = *(const float2*)(qh0 + 8 * ks);
            float2 f1 = *(const float2*)(qh0 + 8 * ks + 8 * DH);
            qah[ks][0] = __float_as_uint(f0.x);
            qah[ks][1] = __float_as_uint(f1.x);
            qah[ks][2] = __float_as_uint(f0.y);
            qah[ks][3] = __float_as_uint(f1.y);
            float2 e0 = *(const float2*)(ql0 + 8 * ks);
            float2 e1 = *(const float2*)(ql0 + 8 * ks + 8 * DH);
            qal[ks][0] = __float_as_uint(e0.x);
            qal[ks][1] = __float_as_uint(e1.x);
            qal[ks][2] = __float_as_uint(e0.y);
            qal[ks][3] = __float_as_uint(e1.y);
        }
    }

    const int p0 = perm8(2 * t);

    // ---- phase 1: scores, no barriers, K frags direct from GMEM ----
    for (int kc = 0; kc < NCH; ++kc) {
        const float* kb = Kh + (size_t)(kc * CK + 8 * wk + g) * DH + 2 * t;
        const float* lb = Kl + (size_t)(kc * CK + 8 * wk + g) * DH + 2 * t;
        float2 fb = *(const float2*)kb;
        float2 fl = *(const float2*)lb;
        float a1[4] = {}, a2[4] = {}, a3[4] = {};
#pragma unroll
        for (int ks = 0; ks < 8; ++ks) {
            unsigned bhf[2] = { __float_as_uint(fb.x), __float_as_uint(fb.y) };
            unsigned blf[2] = { __float_as_uint(fl.x), __float_as_uint(fl.y) };
            if (ks < 7) {
                fb = *(const float2*)(kb + 8 * (ks + 1));
                fl = *(const float2*)(lb + 8 * (ks + 1));
            }
            mma_tf32(a1, qah[ks], bhf);
            mma_tf32(a2, qal[ks], bhf);
            mma_tf32(a3, qah[ks], blf);
        }
        {
            const int bs = kc * CK + 8 * wk;
            const float2 mv = *(const float2*)(mrow + bs + 2 * t);
            const int q = 16 * wq + g;
            float c0 = a1[0] + a2[0] + a3[0];
            float c1 = a1[1] + a2[1] + a3[1];
            float c2 = a1[2] + a2[2] + a3[2];
            float c3 = a1[3] + a2[3] + a3[3];
            sc[q * SCP + bs + p0]           = fmaxf(fmaf(c0, SCALE, mv.x), -10000.0f);
            sc[q * SCP + bs + p0 + 2]       = fmaxf(fmaf(c1, SCALE, mv.y), -10000.0f);
            sc[(q + 8) * SCP + bs + p0]     = fmaxf(fmaf(c2, SCALE, mv.x), -10000.0f);
            sc[(q + 8) * SCP + bs + p0 + 2] = fmaxf(fmaf(c3, SCALE, mv.y), -10000.0f);
        }
    }
    __syncthreads();   // all scores visible

    // ---- phase 2: Michelot sparsemax / softmax, 2 rows per warp ----
    {
        const bool sparse = ((h & 1) == 0);
        float* row0 = sc + warp * SCP;
        float* row1 = sc + (warp + 16) * SCP;
        float z0[32], z1[32];
#pragma unroll
        for (int j = 0; j < 32; ++j) { z0[j] = row0[j * 32 + lane]; z1[j] = row1[j * 32 + lane]; }
        float mx0 = -1e30f, mx1 = -1e30f;
#pragma unroll
        for (int j = 0; j < 32; ++j) { mx0 = fmaxf(mx0, z0[j]); mx1 = fmaxf(mx1, z1[j]); }
        mx0 = warpMax(mx0);
        mx1 = warpMax(mx1);

        if (sparse) {
            float tau0 = mx0 - 1.0f, tau1 = mx1 - 1.0f;
            for (int it = 0; it < 24; ++it) {
                float sa0 = 0.f, sb0 = 0.f, sc0 = 0.f, sd0 = 0.f;
                float ca0 = 0.f, cb0 = 0.f, cc0 = 0.f, cd0 = 0.f;
                float sa1 = 0.f, sb1 = 0.f, sc1 = 0.f, sd1 = 0.f;
                float ca1 = 0.f, cb1 = 0.f, cc1 = 0.f, cd1 = 0.f;
#pragma unroll
                for (int j = 0; j < 32; j += 4) {
                    if (z0[j]     > tau0) { sa0 += z0[j];     ca0 += 1.f; }
                    if (z0[j + 1] > tau0) { sb0 += z0[j + 1]; cb0 += 1.f; }
                    if (z0[j + 2] > tau0) { sc0 += z0[j + 2]; cc0 += 1.f; }
                    if (z0[j + 3] > tau0) { sd0 += z0[j + 3]; cd0 += 1.f; }
                    if (z1[j]     > tau1) { sa1 += z1[j];     ca1 += 1.f; }
                    if (z1[j + 1] > tau1) { sb1 += z1[j + 1]; cb1 += 1.f; }
                    if (z1[j + 2] > tau1) { sc1 += z1[j + 2]; cc1 += 1.f; }
                    if (z1[j + 3] > tau1) { sd1 += z1[j + 3]; cd1 += 1.f; }
                }
                float s0 = (sa0 + sb0) + (sc0 + sd0);
                float c0 = (ca0 + cb0) + (cc0 + cd0);
                float s1 = (sa1 + sb1) + (sc1 + sd1);
                float c1 = (ca1 + cb1) + (cc1 + cd1);
                s0 = warpSum(s0);
                c0 = warpSum(c0);
                s1 = warpSum(s1);
                c1 = warpSum(c1);
                const float nt0 = (s0 - 1.0f) / c0;
                const float nt1 = (s1 - 1.0f) / c1;
                const bool done = (nt0 == tau0) && (nt1 == tau1);
                tau0 = nt0;
                tau1 = nt1;
                if (done) break;
            }
#pragma unroll
            for (int j = 0; j < 32; ++j) {
                row0[j * 32 + lane] = to_tf32(fmaxf(z0[j] - tau0, 0.f));
                row1[j * 32 + lane] = to_tf32(fmaxf(z1[j] - tau1, 0.f));
            }
        } else {
            float s0 = 0.f, s1 = 0.f;
#pragma unroll
            for (int j = 0; j < 32; ++j) {
                z0[j] = __expf(z0[j] - mx0); s0 += z0[j];
                z1[j] = __expf(z1[j] - mx1); s1 += z1[j];
            }
            s0 = warpSum(s0);
            s1 = warpSum(s1);
            const float i0 = 1.0f / s0, i1 = 1.0f / s1;
#pragma unroll
            for (int j = 0; j < 32; ++j) {
                row0[j * 32 + lane] = to_tf32(z0[j] * i0);
                row1[j * 32 + lane] = to_tf32(z1[j] * i1);
            }
        }
    }
    __syncthreads();   // weights visible

    // ---- phase 3: out = weights @ V (hi only), V frags direct from GMEM ----
    float o1[4] = {}, o2[4] = {};
    for (int kc = 0; kc < NCH; ++kc) {
        const float* ab = sc + (16 * wq + g) * SCP + kc * CK + 2 * t;
        const float* vb = Vh + (size_t)(8 * wk + g) * SEQ + kc * CK + 2 * t;
        float2 fa0 = *(const float2*)(ab);
        float2 fa1 = *(const float2*)(ab + 8 * SCP);
        float2 fbh = *(const float2*)(vb);
#pragma unroll
        for (int kk = 0; kk < CK / 8; ++kk) {
            unsigned a[4] = { __float_as_uint(fa0.x), __float_as_uint(fa1.x),
                              __float_as_uint(fa0.y), __float_as_uint(fa1.y) };
            unsigned bhf[2] = { __float_as_uint(fbh.x), __float_as_uint(fbh.y) };
            if (kk < CK / 8 - 1) {
                fa0 = *(const float2*)(ab + 8 * (kk + 1));
                fa1 = *(const float2*)(ab + 8 * SCP + 8 * (kk + 1));
                fbh = *(const float2*)(vb + 8 * (kk + 1));
            }
            mma_tf32((kk & 1) ? o2 : o1, a, bhf);
        }
    }

    // write [B, S, H*HD]
    {
        const int q = q0 + 16 * wq + g;
        float* p = out + (size_t)(b * SEQ + q) * DM + h * DH + 8 * wk + 2 * t;
        *(float2*)p = make_float2(o1[0] + o2[0], o1[1] + o2[1]);
        *(float2*)(p + 8 * DM) = make_float2(o1[2] + o2[2], o1[3] + o2[3]);
    }
}

// ---------------------------------------------------------------------------
extern "C" void kernel_launch(void* const* d_in, const int* in_sizes, int n_in,
                              void* d_out, int out_size) {
    const float* X    = (const float*)d_in[0];
    const float* Wq   = (const float*)d_in[1];
    const float* bq   = (const float*)d_in[2];
    const float* Wk   = (const float*)d_in[3];
    const float* bk   = (const float*)d_in[4];
    const float* Wv   = (const float*)d_in[5];
    const float* bv   = (const float*)d_in[6];
    const float* mask = (const float*)d_in[7];
    float* out = (float*)d_out;

    const int nsplit = (MROWS * DM + 3 * DM * DM) / 4;
    presplit_kernel<<<nsplit / 256, 256>>>(X, Wq, Wk, Wv);

    cudaFuncSetAttribute(qkv_proj_tc, cudaFuncAttributeMaxDynamicSharedMemorySize,
                         PROJ_SMEM_FLOATS * (int)sizeof(float));
    dim3 gp(DM / 128, MROWS / 128, 3);
    qkv_proj_tc<<<gp, 256, PROJ_SMEM_FLOATS * sizeof(float)>>>(bq, bk, bv);

    cudaFuncSetAttribute(attn_tc, cudaFuncAttributeMaxDynamicSharedMemorySize,
                         ATTN_SMEM_FLOATS * (int)sizeof(float));
    dim3 ga(SEQ / TQ, NH, NB);
    attn_tc<<<ga, NT, ATTN_SMEM_FLOATS * sizeof(float)>>>(mask, out);
}

// round 14
// speedup vs baseline: 1.0869x; 1.0869x over previous
#include <cuda_runtime.h>
#include <cstdint>

// Problem constants
#define NB   4
#define SEQ  1024
#define NH   16
#define DH   64
#define DM   1024
#define MROWS (NB * SEQ)

// Pre-split tf32 hi/lo copies of the GEMM inputs.
__device__ float g_xh[MROWS * DM], g_xl[MROWS * DM];
__device__ float g_wh[3 * DM * DM], g_wl[3 * DM * DM];

// Pre-split tf32 hi/lo Q/K ([B,H,S,DH], paired d-permutation) and V hi only
// ([B,H,DH,S] transposed, paired s-permutation).
__device__ float g_qh[NB * NH * SEQ * DH];
__device__ float g_ql[NB * NH * SEQ * DH];
__device__ float g_kh[NB * NH * SEQ * DH];
__device__ float g_kl[NB * NH * SEQ * DH];
__device__ float g_vh[NB * NH * SEQ * DH];

__device__ __forceinline__ int perm8(int x) { return ((x & 3) << 1) | ((x >> 2) & 1); }

__device__ __forceinline__ float to_tf32(float x) {
    unsigned u;
    asm("cvt.rna.tf32.f32 %0, %1;" : "=r"(u) : "f"(x));
    return __uint_as_float(u);
}
__device__ __forceinline__ void split_tf32(float x, float& hi, float& lo) {
    hi = to_tf32(x);
    lo = to_tf32(x - hi);
}
__device__ __forceinline__ void mma_tf32(float* c, const unsigned* a, const unsigned* b) {
    asm volatile(
        "mma.sync.aligned.m16n8k8.row.col.f32.tf32.tf32.f32 "
        "{%0,%1,%2,%3},{%4,%5,%6,%7},{%8,%9},{%0,%1,%2,%3};"
        : "+f"(c[0]), "+f"(c[1]), "+f"(c[2]), "+f"(c[3])
        : "r"(a[0]), "r"(a[1]), "r"(a[2]), "r"(a[3]), "r"(b[0]), "r"(b[1]));
}
__device__ __forceinline__ float warpMax(float v) {
#pragma unroll
    for (int o = 16; o > 0; o >>= 1) v = fmaxf(v, __shfl_xor_sync(0xffffffffu, v, o));
    return v;
}
__device__ __forceinline__ float warpSum(float v) {
#pragma unroll
    for (int o = 16; o > 0; o >>= 1) v += __shfl_xor_sync(0xffffffffu, v, o);
    return v;
}

#define CP_COMMIT() asm volatile("cp.async.commit_group;")
#define CP_WAIT(N)  asm volatile("cp.async.wait_group %0;" :: "n"(N))

__device__ __forceinline__ void cp16(float* dst, const float* src) {
    uint32_t a = (uint32_t)__cvta_generic_to_shared(dst);
    asm volatile("cp.async.cg.shared.global [%0], [%1], 16;" :: "r"(a), "l"(src));
}

// ---------------------------------------------------------------------------
// Pre-split X, Wq, Wk, Wv into tf32 hi/lo device arrays. Memory-bound.
// ---------------------------------------------------------------------------
__global__ __launch_bounds__(256) void presplit_kernel(
    const float* __restrict__ X, const float* __restrict__ Wq,
    const float* __restrict__ Wk, const float* __restrict__ Wv) {
    const size_t NX = (size_t)MROWS * DM / 4;
    const size_t NW = (size_t)DM * DM / 4;
    size_t i = (size_t)blockIdx.x * 256 + threadIdx.x;
    const float4* src;
    float4 *dh, *dl;
    size_t j;
    if (i < NX)               { src = (const float4*)X;  dh = (float4*)g_xh;      dl = (float4*)g_xl;      j = i; }
    else if (i < NX + NW)     { src = (const float4*)Wq; dh = (float4*)g_wh;      dl = (float4*)g_wl;      j = i - NX; }
    else if (i < NX + 2 * NW) { src = (const float4*)Wk; dh = (float4*)g_wh + NW; dl = (float4*)g_wl + NW; j = i - NX - NW; }
    else                      { src = (const float4*)Wv; dh = (float4*)g_wh + 2 * NW; dl = (float4*)g_wl + 2 * NW; j = i - NX - 2 * NW; }
    float4 v = src[j];
    float4 hv, lv;
    split_tf32(v.x, hv.x, lv.x); split_tf32(v.y, hv.y, lv.y);
    split_tf32(v.z, hv.z, lv.z); split_tf32(v.w, hv.w, lv.w);
    dh[j] = hv;
    dl[j] = lv;
}

// ---------------------------------------------------------------------------
// QKV projection, 3xTF32 (R12-proven). 256 threads, 8 warps (64x32 warp
// tiles), CTA tile 128x128, k-stage 16 double-buffered, 2 CTAs/SM.
// ---------------------------------------------------------------------------
constexpr int PKS  = 16;
constexpr int PXS  = 20;
constexpr int PWS  = 136;
constexpr int XSTG = 128 * PXS;
constexpr int WSTG = PKS * PWS;
constexpr int STG  = 2 * XSTG + 2 * WSTG;
constexpr int PROJ_SMEM_FLOATS = 2 * STG;

__device__ __forceinline__ void proj_stage(float* s, const float* xh, const float* xl,
                                           const float* wh, const float* wl,
                                           int m0, int n0, int k0, int tid) {
    float* Xh = s;
    float* Xl = s + XSTG;
    float* Wh = s + 2 * XSTG;
    float* Wl = s + 2 * XSTG + WSTG;
#pragma unroll
    for (int it = 0; it < 2; ++it) {
        const int idx = tid + 256 * it;
        const int r = idx >> 2, c = (idx & 3) << 2;
        const size_t go = (size_t)(m0 + r) * DM + k0 + c;
        cp16(Xh + r * PXS + c, xh + go);
        cp16(Xl + r * PXS + c, xl + go);
    }
#pragma unroll
    for (int it = 0; it < 2; ++it) {
        const int idx = tid + 256 * it;
        const int r = idx >> 5, c = (idx & 31) << 2;
        const size_t go = (size_t)(k0 + r) * DM + n0 + c;
        cp16(Wh + r * PWS + c, wh + go);
        cp16(Wl + r * PWS + c, wl + go);
    }
}

__global__ __launch_bounds__(256, 2) void qkv_proj_tc(
    const float* __restrict__ bq, const float* __restrict__ bk,
    const float* __restrict__ bv) {
    extern __shared__ float psm[];

    const int z = blockIdx.z;
    const float* wh = g_wh + (size_t)z * DM * DM;
    const float* wl = g_wl + (size_t)z * DM * DM;
    const float* bias = (z == 0) ? bq : (z == 1) ? bk : bv;
    float* outh = (z == 0) ? g_qh : (z == 1) ? g_kh : g_vh;
    float* outl = (z == 0) ? g_ql : g_kl;
    const bool isV = (z == 2);

    const int tid = threadIdx.x;
    const int warp = tid >> 5, lane = tid & 31;
    const int g = lane >> 2, t = lane & 3;
    const int wm = (warp >> 2) * 64, wn = (warp & 3) * 32;
    const int m0 = blockIdx.y * 128, n0 = blockIdx.x * 128;

    float acc[4][4][4] = {};

    proj_stage(psm, g_xh, g_xl, wh, wl, m0, n0, 0, tid);
    CP_COMMIT();

    for (int kb = 0; kb < DM / PKS; ++kb) {
        CP_WAIT(0);
        __syncthreads();
        if (kb + 1 < DM / PKS) {
            proj_stage(psm + ((kb + 1) & 1) * STG, g_xh, g_xl, wh, wl,
                       m0, n0, (kb + 1) * PKS, tid);
            CP_COMMIT();
        }
        const float* Xh = psm + (kb & 1) * STG;
        const float* Xl = Xh + XSTG;
        const float* Wh = Xh + 2 * XSTG;
        const float* Wl = Xh + 2 * XSTG + WSTG;

#pragma unroll
        for (int ks = 0; ks < 2; ++ks) {
            unsigned ah[4][4], al[4][4], bh[4][2], bl[4][2];
#pragma unroll
            for (int i = 0; i < 4; ++i) {
                const int off = (wm + 16 * i + g) * PXS + 8 * ks + t;
                ah[i][0] = __float_as_uint(Xh[off]);
                ah[i][1] = __float_as_uint(Xh[off + 8 * PXS]);
                ah[i][2] = __float_as_uint(Xh[off + 4]);
                ah[i][3] = __float_as_uint(Xh[off + 8 * PXS + 4]);
                al[i][0] = __float_as_uint(Xl[off]);
                al[i][1] = __float_as_uint(Xl[off + 8 * PXS]);
                al[i][2] = __float_as_uint(Xl[off + 4]);
                al[i][3] = __float_as_uint(Xl[off + 8 * PXS + 4]);
            }
#pragma unroll
            for (int j = 0; j < 4; ++j) {
                const int off = (8 * ks + t) * PWS + wn + 8 * j + g;
                bh[j][0] = __float_as_uint(Wh[off]);
                bh[j][1] = __float_as_uint(Wh[off + 4 * PWS]);
                bl[j][0] = __float_as_uint(Wl[off]);
                bl[j][1] = __float_as_uint(Wl[off + 4 * PWS]);
            }
#pragma unroll
            for (int i = 0; i < 4; ++i)
#pragma unroll
                for (int j = 0; j < 4; ++j)
                    mma_tf32(acc[i][j], ah[i], bh[j]);
#pragma unroll
            for (int i = 0; i < 4; ++i)
#pragma unroll
                for (int j = 0; j < 4; ++j)
                    mma_tf32(acc[i][j], al[i], bh[j]);
#pragma unroll
            for (int i = 0; i < 4; ++i)
#pragma unroll
                for (int j = 0; j < 4; ++j)
                    mma_tf32(acc[i][j], ah[i], bl[j]);
        }
    }

    // epilogue: + bias, split, scatter into permuted layouts
#pragma unroll
    for (int j = 0; j < 4; ++j) {
        const int n = n0 + wn + 8 * j + 2 * t;
        const float b0v = bias[n], b1v = bias[n + 1];
        const int h = n >> 6, hd = n & 63;
        const int pd = (hd & ~7) | perm8(hd & 7);
#pragma unroll
        for (int i = 0; i < 4; ++i) {
            const int m = m0 + wm + 16 * i + g;
            const int bI = m >> 10, s = m & 1023;
            const int m2 = m + 8;
            const int bI2 = m2 >> 10, s2 = m2 & 1023;
            const float v0 = acc[i][j][0] + b0v;
            const float v1 = acc[i][j][1] + b1v;
            const float v2 = acc[i][j][2] + b0v;
            const float v3 = acc[i][j][3] + b1v;
            if (!isV) {
                float h0, l0, h1, l1, h2, l2, h3, l3;
                split_tf32(v0, h0, l0);
                split_tf32(v1, h1, l1);
                split_tf32(v2, h2, l2);
                split_tf32(v3, h3, l3);
                const size_t b1o = ((size_t)((bI * NH + h) * SEQ + s)) * DH;
                outh[b1o + pd] = h0;  outh[b1o + pd + 2] = h1;
                outl[b1o + pd] = l0;  outl[b1o + pd + 2] = l1;
                const size_t b2o = ((size_t)((bI2 * NH + h) * SEQ + s2)) * DH;
                outh[b2o + pd] = h2;  outh[b2o + pd + 2] = h3;
                outl[b2o + pd] = l2;  outl[b2o + pd + 2] = l3;
            } else {
                const int ps1 = (s & ~7) | perm8(s & 7);
                const int ps2 = (s2 & ~7) | perm8(s2 & 7);
                const size_t r0 = ((size_t)((bI * NH + h) * DH + hd)) * SEQ;
                const size_t r1 = ((size_t)((bI * NH + h) * DH + hd + 1)) * SEQ;
                outh[r0 + ps1] = to_tf32(v0);  outh[r1 + ps1] = to_tf32(v1);
                const size_t r0b = ((size_t)((bI2 * NH + h) * DH + hd)) * SEQ;
                const size_t r1b = ((size_t)((bI2 * NH + h) * DH + hd + 1)) * SEQ;
                outh[r0b + ps2] = to_tf32(v2);  outh[r1b + ps2] = to_tf32(v3);
            }
        }
    }
}

// ---------------------------------------------------------------------------
// Attention, 512 threads. Phase 1: K staged via cp.async double-buffer (R12,
// proven). Phase 2: Michelot sparsemax / softmax. Phase 3: V fragments loaded
// DIRECTLY from GMEM (R13-verified addressing) — no staging, no barriers.
// ---------------------------------------------------------------------------
constexpr int TQ  = 32;
constexpr int CK  = 64;
constexpr int NCH = SEQ / CK;     // 16
constexpr int NT  = 512;
constexpr int APS = 72;
constexpr int SCP = 1032;
constexpr int KVSTG = CK * APS;
constexpr int ATTN_SMEM_FLOATS = TQ * SCP + 2 * TQ * APS + 4 * KVSTG;
constexpr float SCALE = 0.125f;

__device__ __forceinline__ void stage_cp2(float* dh, float* dl,
                                          const float* gh, const float* gl,
                                          int tid, int gstride) {
#pragma unroll
    for (int it = 0; it < 2; ++it) {
        const int idx = tid + 512 * it;
        const int r = idx >> 4, c = (idx & 15) << 2;
        const int so = r * APS + c;
        const size_t go = (size_t)r * gstride + c;
        cp16(dh + so, gh + go);
        cp16(dl + so, gl + go);
    }
}

__global__ __launch_bounds__(NT, 1) void attn_tc(const float* __restrict__ mask,
                                                 float* __restrict__ out) {
    extern __shared__ float sm[];
    float* sc  = sm;                    // [TQ][SCP]
    float* qsh = sm + TQ * SCP;         // [TQ][APS]
    float* qsl = qsh + TQ * APS;
    float* kv  = qsl + TQ * APS;

    float* kvH[2] = { kv, kv + 2 * KVSTG };
    float* kvL[2] = { kv + KVSTG, kv + 3 * KVSTG };

    const int tid = threadIdx.x;
    const int b = blockIdx.z, h = blockIdx.y;
    const int q0 = blockIdx.x * TQ;
    const int bh_i = b * NH + h;
    const float* Qh = g_qh + ((size_t)bh_i * SEQ + q0) * DH;
    const float* Ql = g_ql + ((size_t)bh_i * SEQ + q0) * DH;
    const float* Kh = g_kh + (size_t)bh_i * SEQ * DH;
    const float* Kl = g_kl + (size_t)bh_i * SEQ * DH;
    const float* Vh = g_vh + (size_t)bh_i * DH * SEQ;
    const float* mrow = mask + b * SEQ;

    const int warp = tid >> 5, lane = tid & 31;
    const int g = lane >> 2, t = lane & 3;
    const int wq = warp >> 3;
    const int wk = warp & 7;

    stage_cp2(kvH[0], kvL[0], Kh, Kl, tid, DH);
    CP_COMMIT();
    {
        const int e = tid << 2;
        const int qi = e >> 6, dd = e & 63;
        *(float4*)(qsh + qi * APS + dd) = *(const float4*)(Qh + e);
        *(float4*)(qsl + qi * APS + dd) = *(const float4*)(Ql + e);
    }
    __syncthreads();

    unsigned qah[8][4], qal[8][4];
#pragma unroll
    for (int ks = 0; ks < 8; ++ks) {
        const int off = (16 * wq + g) * APS + 8 * ks + 2 * t;
        float2 f0 = *(const float2*)(qsh + off);
        float2 f1 = *(const float2*)(qsh + off + 8 * APS);
        qah[ks][0] = __float_as_uint(f0.x);
        qah[ks][1] = __float_as_uint(f1.x);
        qah[ks][2] = __float_as_uint(f0.y);
        qah[ks][3] = __float_as_uint(f1.y);
        float2 e0 = *(const float2*)(qsl + off);
        float2 e1 = *(const float2*)(qsl + off + 8 * APS);
        qal[ks][0] = __float_as_uint(e0.x);
        qal[ks][1] = __float_as_uint(e1.x);
        qal[ks][2] = __float_as_uint(e0.y);
        qal[ks][3] = __float_as_uint(e1.y);
    }

    const int p0 = perm8(2 * t);

    // ---- phase 1: scores (R12 staging pipeline, proven) ----
    for (int kc = 0; kc < NCH; ++kc) {
        CP_WAIT(0);
        __syncthreads();
        if (kc + 1 < NCH) {
            stage_cp2(kvH[(kc + 1) & 1], kvL[(kc + 1) & 1],
                      Kh + (size_t)(kc + 1) * CK * DH, Kl + (size_t)(kc + 1) * CK * DH,
                      tid, DH);
            CP_COMMIT();
        }

        const float* bH = kvH[kc & 1];
        const float* bL = kvL[kc & 1];
        float a1[4] = {}, a2[4] = {}, a3[4] = {};
#pragma unroll
        for (int ks = 0; ks < 8; ++ks) {
            const int boff = (8 * wk + g) * APS + 8 * ks + 2 * t;
            float2 fb = *(const float2*)(bH + boff);
            float2 fl = *(const float2*)(bL + boff);
            unsigned bhf[2] = { __float_as_uint(fb.x), __float_as_uint(fb.y) };
            unsigned blf[2] = { __float_as_uint(fl.x), __float_as_uint(fl.y) };
            mma_tf32(a1, qah[ks], bhf);
            mma_tf32(a2, qal[ks], bhf);
            mma_tf32(a3, qah[ks], blf);
        }
        {
            const int bs = kc * CK + 8 * wk;
            const float2 mv = *(const float2*)(mrow + bs + 2 * t);
            const int q = 16 * wq + g;
            float c0 = a1[0] + a2[0] + a3[0];
            float c1 = a1[1] + a2[1] + a3[1];
            float c2 = a1[2] + a2[2] + a3[2];
            float c3 = a1[3] + a2[3] + a3[3];
            sc[q * SCP + bs + p0]           = fmaxf(fmaf(c0, SCALE, mv.x), -10000.0f);
            sc[q * SCP + bs + p0 + 2]       = fmaxf(fmaf(c1, SCALE, mv.y), -10000.0f);
            sc[(q + 8) * SCP + bs + p0]     = fmaxf(fmaf(c2, SCALE, mv.x), -10000.0f);
            sc[(q + 8) * SCP + bs + p0 + 2] = fmaxf(fmaf(c3, SCALE, mv.y), -10000.0f);
        }
    }
    __syncthreads();   // all scores visible

    // ---- phase 2: Michelot sparsemax / softmax, 2 rows per warp ----
    {
        const bool sparse = ((h & 1) == 0);
        float* row0 = sc + warp * SCP;
        float* row1 = sc + (warp + 16) * SCP;
        float z0[32], z1[32];
#pragma unroll
        for (int j = 0; j < 32; ++j) { z0[j] = row0[j * 32 + lane]; z1[j] = row1[j * 32 + lane]; }
        float mx0 = -1e30f, mx1 = -1e30f;
#pragma unroll
        for (int j = 0; j < 32; ++j) { mx0 = fmaxf(mx0, z0[j]); mx1 = fmaxf(mx1, z1[j]); }
        mx0 = warpMax(mx0);
        mx1 = warpMax(mx1);

        if (sparse) {
            float tau0 = mx0 - 1.0f, tau1 = mx1 - 1.0f;
            for (int it = 0; it < 24; ++it) {
                float sa0 = 0.f, sb0 = 0.f, sc0 = 0.f, sd0 = 0.f;
                float ca0 = 0.f, cb0 = 0.f, cc0 = 0.f, cd0 = 0.f;
                float sa1 = 0.f, sb1 = 0.f, sc1 = 0.f, sd1 = 0.f;
                float ca1 = 0.f, cb1 = 0.f, cc1 = 0.f, cd1 = 0.f;
#pragma unroll
                for (int j = 0; j < 32; j += 4) {
                    if (z0[j]     > tau0) { sa0 += z0[j];     ca0 += 1.f; }
                    if (z0[j + 1] > tau0) { sb0 += z0[j + 1]; cb0 += 1.f; }
                    if (z0[j + 2] > tau0) { sc0 += z0[j + 2]; cc0 += 1.f; }
                    if (z0[j + 3] > tau0) { sd0 += z0[j + 3]; cd0 += 1.f; }
                    if (z1[j]     > tau1) { sa1 += z1[j];     ca1 += 1.f; }
                    if (z1[j + 1] > tau1) { sb1 += z1[j + 1]; cb1 += 1.f; }
                    if (z1[j + 2] > tau1) { sc1 += z1[j + 2]; cc1 += 1.f; }
                    if (z1[j + 3] > tau1) { sd1 += z1[j + 3]; cd1 += 1.f; }
                }
                float s0 = (sa0 + sb0) + (sc0 + sd0);
                float c0 = (ca0 + cb0) + (cc0 + cd0);
                float s1 = (sa1 + sb1) + (sc1 + sd1);
                float c1 = (ca1 + cb1) + (cc1 + cd1);
                s0 = warpSum(s0);
                c0 = warpSum(c0);
                s1 = warpSum(s1);
                c1 = warpSum(c1);
                const float nt0 = (s0 - 1.0f) / c0;
                const float nt1 = (s1 - 1.0f) / c1;
                const bool done = (nt0 == tau0) && (nt1 == tau1);
                tau0 = nt0;
                tau1 = nt1;
                if (done) break;
            }
#pragma unroll
            for (int j = 0; j < 32; ++j) {
                row0[j * 32 + lane] = to_tf32(fmaxf(z0[j] - tau0, 0.f));
                row1[j * 32 + lane] = to_tf32(fmaxf(z1[j] - tau1, 0.f));
            }
        } else {
            float s0 = 0.f, s1 = 0.f;
#pragma unroll
            for (int j = 0; j < 32; ++j) {
                z0[j] = __expf(z0[j] - mx0); s0 += z0[j];
                z1[j] = __expf(z1[j] - mx1); s1 += z1[j];
            }
            s0 = warpSum(s0);
            s1 = warpSum(s1);
            const float i0 = 1.0f / s0, i1 = 1.0f / s1;
#pragma unroll
            for (int j = 0; j < 32; ++j) {
                row0[j * 32 + lane] = to_tf32(z0[j] * i0);
                row1[j * 32 + lane] = to_tf32(z1[j] * i1);
            }
        }
    }
    __syncthreads();   // weights visible

    // ---- phase 3: out = weights @ V, V frags DIRECT from GMEM (verified) ----
    float o1[4] = {}, o2[4] = {};
    for (int kc = 0; kc < NCH; ++kc) {
        const float* ab = sc + (16 * wq + g) * SCP + kc * CK + 2 * t;
        const float* vb = Vh + (size_t)(8 * wk + g) * SEQ + kc * CK + 2 * t;
        float2 fa0 = *(const float2*)(ab);
        float2 fa1 = *(const float2*)(ab + 8 * SCP);
        float2 fbh = *(const float2*)(vb);
#pragma unroll
        for (int kk = 0; kk < CK / 8; ++kk) {
            unsigned a[4] = { __float_as_uint(fa0.x), __float_as_uint(fa1.x),
                              __float_as_uint(fa0.y), __float_as_uint(fa1.y) };
            unsigned bhf[2] = { __float_as_uint(fbh.x), __float_as_uint(fbh.y) };
            if (kk < CK / 8 - 1) {
                fa0 = *(const float2*)(ab + 8 * (kk + 1));
                fa1 = *(const float2*)(ab + 8 * SCP + 8 * (kk + 1));
                fbh = *(const float2*)(vb + 8 * (kk + 1));
            }
            mma_tf32((kk & 1) ? o2 : o1, a, bhf);
        }
    }

    // write [B, S, H*HD]
    {
        const int q = q0 + 16 * wq + g;
        float* p = out + (size_t)(b * SEQ + q) * DM + h * DH + 8 * wk + 2 * t;
        *(float2*)p = make_float2(o1[0] + o2[0], o1[1] + o2[1]);
        *(float2*)(p + 8 * DM) = make_float2(o1[2] + o2[2], o1[3] + o2[3]);
    }
}

// ---------------------------------------------------------------------------
extern "C" void kernel_launch(void* const* d_in, const int* in_sizes, int n_in,
                              void* d_out, int out_size) {
    const float* X    = (const float*)d_in[0];
    const float* Wq   = (const float*)d_in[1];
    const float* bq   = (const float*)d_in[2];
    const float* Wk   = (const float*)d_in[3];
    const float* bk   = (const float*)d_in[4];
    const float* Wv   = (const float*)d_in[5];
    const float* bv   = (const float*)d_in[6];
    const float* mask = (const float*)d_in[7];
    float* out = (float*)d_out;

    const int nsplit = (MROWS * DM + 3 * DM * DM) / 4;
    presplit_kernel<<<nsplit / 256, 256>>>(X, Wq, Wk, Wv);

    cudaFuncSetAttribute(qkv_proj_tc, cudaFuncAttributeMaxDynamicSharedMemorySize,
                         PROJ_SMEM_FLOATS * (int)sizeof(float));
    dim3 gp(DM / 128, MROWS / 128, 3);
    qkv_proj_tc<<<gp, 256, PROJ_SMEM_FLOATS * sizeof(float)>>>(bq, bk, bv);

    cudaFuncSetAttribute(attn_tc, cudaFuncAttributeMaxDynamicSharedMemorySize,
                         ATTN_SMEM_FLOATS * (int)sizeof(float));
    dim3 ga(SEQ / TQ, NH, NB);
    attn_tc<<<ga, NT, ATTN_SMEM_FLOATS * sizeof(float)>>>(mask, out);
}

// round 15
// speedup vs baseline: 1.4866x; 1.3677x over previous
#include <cuda_runtime.h>
#include <cuda_bf16.h>
#include <cstdint>

// Problem constants
#define NB   4
#define SEQ  1024
#define NH   16
#define DH   64
#define DM   1024
#define MROWS (NB * SEQ)

// bf16 hi/lo pre-split GEMM inputs. X: [m][k]; W: TRANSPOSED [n][k]. Both with
// pair-permutation inside each 16-k block (pair p -> pos ((p&3)<<1)|(p>>2)).
__device__ __nv_bfloat16 g_xbh[MROWS * DM], g_xbl[MROWS * DM];
__device__ __nv_bfloat16 g_wbh[3 * DM * DM], g_wbl[3 * DM * DM];

// Pre-split tf32 hi/lo Q/K ([B,H,S,DH], paired d-permutation) and V hi only
// ([B,H,DH,S] transposed, paired s-permutation). Consumed by attention (R12).
__device__ float g_qh[NB * NH * SEQ * DH];
__device__ float g_ql[NB * NH * SEQ * DH];
__device__ float g_kh[NB * NH * SEQ * DH];
__device__ float g_kl[NB * NH * SEQ * DH];
__device__ float g_vh[NB * NH * SEQ * DH];

__device__ __forceinline__ int perm8(int x) { return ((x & 3) << 1) | ((x >> 2) & 1); }

__device__ __forceinline__ float to_tf32(float x) {
    unsigned u;
    asm("cvt.rna.tf32.f32 %0, %1;" : "=r"(u) : "f"(x));
    return __uint_as_float(u);
}
__device__ __forceinline__ void split_tf32(float x, float& hi, float& lo) {
    hi = to_tf32(x);
    lo = to_tf32(x - hi);
}
__device__ __forceinline__ void split_bf16(float x, __nv_bfloat16& hi, __nv_bfloat16& lo) {
    hi = __float2bfloat16(x);
    lo = __float2bfloat16(x - __bfloat162float(hi));
}
__device__ __forceinline__ void mma_tf32(float* c, const unsigned* a, const unsigned* b) {
    asm volatile(
        "mma.sync.aligned.m16n8k8.row.col.f32.tf32.tf32.f32 "
        "{%0,%1,%2,%3},{%4,%5,%6,%7},{%8,%9},{%0,%1,%2,%3};"
        : "+f"(c[0]), "+f"(c[1]), "+f"(c[2]), "+f"(c[3])
        : "r"(a[0]), "r"(a[1]), "r"(a[2]), "r"(a[3]), "r"(b[0]), "r"(b[1]));
}
__device__ __forceinline__ void mma_bf16(float* c, const unsigned* a, const unsigned* b) {
    asm volatile(
        "mma.sync.aligned.m16n8k16.row.col.f32.bf16.bf16.f32 "
        "{%0,%1,%2,%3},{%4,%5,%6,%7},{%8,%9},{%0,%1,%2,%3};"
        : "+f"(c[0]), "+f"(c[1]), "+f"(c[2]), "+f"(c[3])
        : "r"(a[0]), "r"(a[1]), "r"(a[2]), "r"(a[3]), "r"(b[0]), "r"(b[1]));
}
__device__ __forceinline__ float warpMax(float v) {
#pragma unroll
    for (int o = 16; o > 0; o >>= 1) v = fmaxf(v, __shfl_xor_sync(0xffffffffu, v, o));
    return v;
}
__device__ __forceinline__ float warpSum(float v) {
#pragma unroll
    for (int o = 16; o > 0; o >>= 1) v += __shfl_xor_sync(0xffffffffu, v, o);
    return v;
}

#define CP_COMMIT() asm volatile("cp.async.commit_group;")
#define CP_WAIT(N)  asm volatile("cp.async.wait_group %0;" :: "n"(N))

__device__ __forceinline__ void cp16(void* dst, const void* src) {
    uint32_t a = (uint32_t)__cvta_generic_to_shared(dst);
    asm volatile("cp.async.cg.shared.global [%0], [%1], 16;" :: "r"(a), "l"(src));
}

// ---------------------------------------------------------------------------
// Presplit X -> bf16 hi/lo [m][k], pair-permuted per 16-k block.
// ---------------------------------------------------------------------------
__global__ __launch_bounds__(256) void presplit_x(const float* __restrict__ X) {
    const int idx = blockIdx.x * 256 + threadIdx.x;   // one float4 each
    const int row = idx >> 8;                          // DM/4 = 256 float4 per row
    const int k4 = (idx & 255) << 2;
    float4 v = ((const float4*)X)[idx];
    const int kb = k4 & ~15;
    const int p0 = (k4 & 15) >> 1;
    const int p1 = p0 + 1;
    const int q0 = ((p0 & 3) << 1) | (p0 >> 2);
    const int q1 = ((p1 & 3) << 1) | (p1 >> 2);
    __nv_bfloat16 hx, lx, hy, ly, hz, lz, hw, lw;
    split_bf16(v.x, hx, lx); split_bf16(v.y, hy, ly);
    split_bf16(v.z, hz, lz); split_bf16(v.w, hw, lw);
    __nv_bfloat162* dh = (__nv_bfloat162*)(g_xbh + (size_t)row * DM + kb);
    __nv_bfloat162* dl = (__nv_bfloat162*)(g_xbl + (size_t)row * DM + kb);
    dh[q0] = __nv_bfloat162(hx, hy);
    dl[q0] = __nv_bfloat162(lx, ly);
    dh[q1] = __nv_bfloat162(hz, hw);
    dl[q1] = __nv_bfloat162(lz, lw);
}

// ---------------------------------------------------------------------------
// Presplit + TRANSPOSE W -> bf16 hi/lo [n][k], pair-permuted. smem-tiled 64x64.
// ---------------------------------------------------------------------------
__global__ __launch_bounds__(256) void presplit_wt(
    const float* __restrict__ Wq, const float* __restrict__ Wk,
    const float* __restrict__ Wv) {
    __shared__ __nv_bfloat16 sh[64 * 80], sl[64 * 80];
    const int z = blockIdx.z;
    const float* W = (z == 0) ? Wq : (z == 1) ? Wk : Wv;
    const size_t zo = (size_t)z * DM * DM;
    const int k0 = blockIdx.x * 64, n0 = blockIdx.y * 64;
    const int tid = threadIdx.x;
#pragma unroll
    for (int it = 0; it < 16; ++it) {
        const int e = tid + 256 * it;
        const int kk = e >> 6, nn = e & 63;
        float x = W[(size_t)(k0 + kk) * DM + n0 + nn];
        __nv_bfloat16 hi, lo;
        split_bf16(x, hi, lo);
        const int b16 = kk & ~15;
        const int p = (kk & 15) >> 1;
        const int q = ((p & 3) << 1) | (p >> 2);
        const int skk = b16 + (q << 1) + (kk & 1);
        sh[nn * 80 + skk] = hi;
        sl[nn * 80 + skk] = lo;
    }
    __syncthreads();
#pragma unroll
    for (int it = 0; it < 2; ++it) {
        const int e = tid + 256 * it;
        const int rr = e >> 3, cc = e & 7;   // 64 rows x 8 chunks of 8 bf16
        *(uint4*)(g_wbh + zo + (size_t)(n0 + rr) * DM + k0 + cc * 8) =
            *(const uint4*)(sh + rr * 80 + cc * 8);
        *(uint4*)(g_wbl + zo + (size_t)(n0 + rr) * DM + k0 + cc * 8) =
            *(const uint4*)(sl + rr * 80 + cc * 8);
    }
}

// ---------------------------------------------------------------------------
// QKV projection, 3xBF16 m16n8k16. 256 threads, 8 warps (64x32 warp tiles),
// CTA tile 128x128, k-stage 32 double-buffered (96 KB), 2 CTAs/SM.
// Epilogue identical to R12 (fp32 acc -> tf32-split Q/K, tf32 V transposed).
// ---------------------------------------------------------------------------
constexpr int BST  = 48;               // smem row stride in bf16 (96B: conflict-free)
constexpr int BXS  = 128 * BST;        // bf16 per buffer (X or W, hi or lo)
constexpr int BSTG = 4 * BXS;          // Xh,Xl,Wh,Wl per stage = 24576 bf16
constexpr int PROJ_SMEM_BYTES = 2 * BSTG * 2;   // 96 KB

__device__ __forceinline__ void pstage(__nv_bfloat16* s,
                                       const __nv_bfloat16* xh, const __nv_bfloat16* xl,
                                       const __nv_bfloat16* wh, const __nv_bfloat16* wl,
                                       int m0, int n0, int k0, int tid) {
    __nv_bfloat16* Xh = s;
    __nv_bfloat16* Xl = s + BXS;
    __nv_bfloat16* Wh = s + 2 * BXS;
    __nv_bfloat16* Wl = s + 3 * BXS;
#pragma unroll
    for (int it = 0; it < 2; ++it) {
        const int idx = tid + 256 * it;
        const int r = idx >> 2, c = (idx & 3) << 3;   // 4 chunks of 8 bf16 (16B)
        const size_t gx = (size_t)(m0 + r) * DM + k0 + c;
        cp16(Xh + r * BST + c, xh + gx);
        cp16(Xl + r * BST + c, xl + gx);
        const size_t gw = (size_t)(n0 + r) * DM + k0 + c;
        cp16(Wh + r * BST + c, wh + gw);
        cp16(Wl + r * BST + c, wl + gw);
    }
}

__global__ __launch_bounds__(256, 2) void qkv_proj_tc(
    const float* __restrict__ bq, const float* __restrict__ bk,
    const float* __restrict__ bv) {
    extern __shared__ __nv_bfloat16 bsm[];

    const int z = blockIdx.z;
    const __nv_bfloat16* wbh = g_wbh + (size_t)z * DM * DM;
    const __nv_bfloat16* wbl = g_wbl + (size_t)z * DM * DM;
    const float* bias = (z == 0) ? bq : (z == 1) ? bk : bv;
    float* outh = (z == 0) ? g_qh : (z == 1) ? g_kh : g_vh;
    float* outl = (z == 0) ? g_ql : g_kl;     // unused for V
    const bool isV = (z == 2);

    const int tid = threadIdx.x;
    const int warp = tid >> 5, lane = tid & 31;
    const int g = lane >> 2, t = lane & 3;
    const int wm = (warp >> 2) * 64, wn = (warp & 3) * 32;
    const int m0 = blockIdx.y * 128, n0 = blockIdx.x * 128;

    float acc[4][4][4] = {};

    pstage(bsm, g_xbh, g_xbl, wbh, wbl, m0, n0, 0, tid);
    CP_COMMIT();

    for (int kb = 0; kb < DM / 32; ++kb) {
        CP_WAIT(0);
        __syncthreads();
        if (kb + 1 < DM / 32) {
            pstage(bsm + ((kb + 1) & 1) * BSTG, g_xbh, g_xbl, wbh, wbl,
                   m0, n0, (kb + 1) * 32, tid);
            CP_COMMIT();
        }
        const __nv_bfloat16* Xh = bsm + (kb & 1) * BSTG;
        const __nv_bfloat16* Xl = Xh + BXS;
        const __nv_bfloat16* Wh = Xh + 2 * BXS;
        const __nv_bfloat16* Wl = Xh + 3 * BXS;

#pragma unroll
        for (int ks = 0; ks < 2; ++ks) {
            unsigned ah[4][4], al[4][4], bh[4][2], bl[4][2];
#pragma unroll
            for (int i = 0; i < 4; ++i) {
                const int base = (wm + 16 * i + g) * BST + ks * 16 + 4 * t;
                uint2 u0 = *(const uint2*)(Xh + base);
                uint2 u1 = *(const uint2*)(Xh + base + 8 * BST);
                ah[i][0] = u0.x; ah[i][1] = u1.x; ah[i][2] = u0.y; ah[i][3] = u1.y;
                uint2 e0 = *(const uint2*)(Xl + base);
                uint2 e1 = *(const uint2*)(Xl + base + 8 * BST);
                al[i][0] = e0.x; al[i][1] = e1.x; al[i][2] = e0.y; al[i][3] = e1.y;
            }
#pragma unroll
            for (int j = 0; j < 4; ++j) {
                const int base = (wn + 8 * j + g) * BST + ks * 16 + 4 * t;
                uint2 u = *(const uint2*)(Wh + base);
                bh[j][0] = u.x; bh[j][1] = u.y;
                uint2 e = *(const uint2*)(Wl + base);
                bl[j][0] = e.x; bl[j][1] = e.y;
            }
            // three sweeps of 16 independent MMAs
#pragma unroll
            for (int i = 0; i < 4; ++i)
#pragma unroll
                for (int j = 0; j < 4; ++j)
                    mma_bf16(acc[i][j], ah[i], bh[j]);
#pragma unroll
            for (int i = 0; i < 4; ++i)
#pragma unroll
                for (int j = 0; j < 4; ++j)
                    mma_bf16(acc[i][j], al[i], bh[j]);
#pragma unroll
            for (int i = 0; i < 4; ++i)
#pragma unroll
                for (int j = 0; j < 4; ++j)
                    mma_bf16(acc[i][j], ah[i], bl[j]);
        }
    }

    // epilogue: + bias, split, scatter into permuted layouts (R12 verbatim)
#pragma unroll
    for (int j = 0; j < 4; ++j) {
        const int n = n0 + wn + 8 * j + 2 * t;
        const float b0v = bias[n], b1v = bias[n + 1];
        const int h = n >> 6, hd = n & 63;
        const int pd = (hd & ~7) | perm8(hd & 7);
#pragma unroll
        for (int i = 0; i < 4; ++i) {
            const int m = m0 + wm + 16 * i + g;
            const int bI = m >> 10, s = m & 1023;
            const int m2 = m + 8;
            const int bI2 = m2 >> 10, s2 = m2 & 1023;
            const float v0 = acc[i][j][0] + b0v;
            const float v1 = acc[i][j][1] + b1v;
            const float v2 = acc[i][j][2] + b0v;
            const float v3 = acc[i][j][3] + b1v;
            if (!isV) {
                float h0, l0, h1, l1, h2, l2, h3, l3;
                split_tf32(v0, h0, l0);
                split_tf32(v1, h1, l1);
                split_tf32(v2, h2, l2);
                split_tf32(v3, h3, l3);
                const size_t b1o = ((size_t)((bI * NH + h) * SEQ + s)) * DH;
                outh[b1o + pd] = h0;  outh[b1o + pd + 2] = h1;
                outl[b1o + pd] = l0;  outl[b1o + pd + 2] = l1;
                const size_t b2o = ((size_t)((bI2 * NH + h) * SEQ + s2)) * DH;
                outh[b2o + pd] = h2;  outh[b2o + pd + 2] = h3;
                outl[b2o + pd] = l2;  outl[b2o + pd + 2] = l3;
            } else {
                const int ps1 = (s & ~7) | perm8(s & 7);
                const int ps2 = (s2 & ~7) | perm8(s2 & 7);
                const size_t r0 = ((size_t)((bI * NH + h) * DH + hd)) * SEQ;
                const size_t r1 = ((size_t)((bI * NH + h) * DH + hd + 1)) * SEQ;
                outh[r0 + ps1] = to_tf32(v0);  outh[r1 + ps1] = to_tf32(v1);
                const size_t r0b = ((size_t)((bI2 * NH + h) * DH + hd)) * SEQ;
                const size_t r1b = ((size_t)((bI2 * NH + h) * DH + hd + 1)) * SEQ;
                outh[r0b + ps2] = to_tf32(v2);  outh[r1b + ps2] = to_tf32(v3);
            }
        }
    }
}

// ---------------------------------------------------------------------------
// Attention — R12-proven version VERBATIM. 512 threads, cp.async double-
// buffer, 1 barrier/chunk, Michelot sparsemax, phase 3 staged V (hi only).
// ---------------------------------------------------------------------------
constexpr int TQ  = 32;
constexpr int CK  = 64;
constexpr int NCH = SEQ / CK;     // 16
constexpr int NT  = 512;
constexpr int APS = 72;
constexpr int SCP = 1032;
constexpr int KVSTG = CK * APS;
constexpr int ATTN_SMEM_FLOATS = TQ * SCP + 2 * TQ * APS + 4 * KVSTG;
constexpr float SCALE = 0.125f;

__device__ __forceinline__ void stage_cp2(float* dh, float* dl,
                                          const float* gh, const float* gl,
                                          int tid, int gstride) {
#pragma unroll
    for (int it = 0; it < 2; ++it) {
        const int idx = tid + 512 * it;
        const int r = idx >> 4, c = (idx & 15) << 2;
        const int so = r * APS + c;
        const size_t go = (size_t)r * gstride + c;
        cp16(dh + so, gh + go);
        cp16(dl + so, gl + go);
    }
}
__device__ __forceinline__ void stage_cp1(float* dh, const float* gh,
                                          int tid, int gstride) {
#pragma unroll
    for (int it = 0; it < 2; ++it) {
        const int idx = tid + 512 * it;
        const int r = idx >> 4, c = (idx & 15) << 2;
        cp16(dh + r * APS + c, gh + (size_t)r * gstride + c);
    }
}

__global__ __launch_bounds__(NT, 1) void attn_tc(const float* __restrict__ mask,
                                                 float* __restrict__ out) {
    extern __shared__ float sm[];
    float* sc  = sm;                    // [TQ][SCP]
    float* qsh = sm + TQ * SCP;         // [TQ][APS]
    float* qsl = qsh + TQ * APS;
    float* kv  = qsl + TQ * APS;

    float* kvH[2] = { kv, kv + 2 * KVSTG };
    float* kvL[2] = { kv + KVSTG, kv + 3 * KVSTG };

    const int tid = threadIdx.x;
    const int b = blockIdx.z, h = blockIdx.y;
    const int q0 = blockIdx.x * TQ;
    const int bh_i = b * NH + h;
    const float* Qh = g_qh + ((size_t)bh_i * SEQ + q0) * DH;
    const float* Ql = g_ql + ((size_t)bh_i * SEQ + q0) * DH;
    const float* Kh = g_kh + (size_t)bh_i * SEQ * DH;
    const float* Kl = g_kl + (size_t)bh_i * SEQ * DH;
    const float* Vh = g_vh + (size_t)bh_i * DH * SEQ;
    const float* mrow = mask + b * SEQ;

    const int warp = tid >> 5, lane = tid & 31;
    const int g = lane >> 2, t = lane & 3;
    const int wq = warp >> 3;
    const int wk = warp & 7;

    stage_cp2(kvH[0], kvL[0], Kh, Kl, tid, DH);
    CP_COMMIT();
    {
        const int e = tid << 2;
        const int qi = e >> 6, dd = e & 63;
        *(float4*)(qsh + qi * APS + dd) = *(const float4*)(Qh + e);
        *(float4*)(qsl + qi * APS + dd) = *(const float4*)(Ql + e);
    }
    __syncthreads();

    unsigned qah[8][4], qal[8][4];
#pragma unroll
    for (int ks = 0; ks < 8; ++ks) {
        const int off = (16 * wq + g) * APS + 8 * ks + 2 * t;
        float2 f0 = *(const float2*)(qsh + off);
        float2 f1 = *(const float2*)(qsh + off + 8 * APS);
        qah[ks][0] = __float_as_uint(f0.x);
        qah[ks][1] = __float_as_uint(f1.x);
        qah[ks][2] = __float_as_uint(f0.y);
        qah[ks][3] = __float_as_uint(f1.y);
        float2 e0 = *(const float2*)(qsl + off);
        float2 e1 = *(const float2*)(qsl + off + 8 * APS);
        qal[ks][0] = __float_as_uint(e0.x);
        qal[ks][1] = __float_as_uint(e1.x);
        qal[ks][2] = __float_as_uint(e0.y);
        qal[ks][3] = __float_as_uint(e1.y);
    }

    const int p0 = perm8(2 * t);

    // ---- phase 1: scores ----
    for (int kc = 0; kc < NCH; ++kc) {
        CP_WAIT(0);
        __syncthreads();
        if (kc + 1 < NCH) {
            stage_cp2(kvH[(kc + 1) & 1], kvL[(kc + 1) & 1],
                      Kh + (size_t)(kc + 1) * CK * DH, Kl + (size_t)(kc + 1) * CK * DH,
                      tid, DH);
            CP_COMMIT();
        }

        const float* bH = kvH[kc & 1];
        const float* bL = kvL[kc & 1];
        float a1[4] = {}, a2[4] = {}, a3[4] = {};
#pragma unroll
        for (int ks = 0; ks < 8; ++ks) {
            const int boff = (8 * wk + g) * APS + 8 * ks + 2 * t;
            float2 fb = *(const float2*)(bH + boff);
            float2 fl = *(const float2*)(bL + boff);
            unsigned bhf[2] = { __float_as_uint(fb.x), __float_as_uint(fb.y) };
            unsigned blf[2] = { __float_as_uint(fl.x), __float_as_uint(fl.y) };
            mma_tf32(a1, qah[ks], bhf);
            mma_tf32(a2, qal[ks], bhf);
            mma_tf32(a3, qah[ks], blf);
        }
        {
            const int bs = kc * CK + 8 * wk;
            const float2 mv = *(const float2*)(mrow + bs + 2 * t);
            const int q = 16 * wq + g;
            float c0 = a1[0] + a2[0] + a3[0];
            float c1 = a1[1] + a2[1] + a3[1];
            float c2 = a1[2] + a2[2] + a3[2];
            float c3 = a1[3] + a2[3] + a3[3];
            sc[q * SCP + bs + p0]           = fmaxf(fmaf(c0, SCALE, mv.x), -10000.0f);
            sc[q * SCP + bs + p0 + 2]       = fmaxf(fmaf(c1, SCALE, mv.y), -10000.0f);
            sc[(q + 8) * SCP + bs + p0]     = fmaxf(fmaf(c2, SCALE, mv.x), -10000.0f);
            sc[(q + 8) * SCP + bs + p0 + 2] = fmaxf(fmaf(c3, SCALE, mv.y), -10000.0f);
        }
    }

    stage_cp1(kvH[0], Vh, tid, SEQ);
    CP_COMMIT();
    __syncthreads();

    // ---- phase 2: Michelot sparsemax / softmax, 2 rows per warp ----
    {
        const bool sparse = ((h & 1) == 0);
        float* row0 = sc + warp * SCP;
        float* row1 = sc + (warp + 16) * SCP;
        float z0[32], z1[32];
#pragma unroll
        for (int j = 0; j < 32; ++j) { z0[j] = row0[j * 32 + lane]; z1[j] = row1[j * 32 + lane]; }
        float mx0 = -1e30f, mx1 = -1e30f;
#pragma unroll
        for (int j = 0; j < 32; ++j) { mx0 = fmaxf(mx0, z0[j]); mx1 = fmaxf(mx1, z1[j]); }
        mx0 = warpMax(mx0);
        mx1 = warpMax(mx1);

        if (sparse) {
            float tau0 = mx0 - 1.0f, tau1 = mx1 - 1.0f;
            for (int it = 0; it < 24; ++it) {
                float sa0 = 0.f, sb0 = 0.f, sc0 = 0.f, sd0 = 0.f;
                float ca0 = 0.f, cb0 = 0.f, cc0 = 0.f, cd0 = 0.f;
                float sa1 = 0.f, sb1 = 0.f, sc1 = 0.f, sd1 = 0.f;
                float ca1 = 0.f, cb1 = 0.f, cc1 = 0.f, cd1 = 0.f;
#pragma unroll
                for (int j = 0; j < 32; j += 4) {
                    if (z0[j]     > tau0) { sa0 += z0[j];     ca0 += 1.f; }
                    if (z0[j + 1] > tau0) { sb0 += z0[j + 1]; cb0 += 1.f; }
                    if (z0[j + 2] > tau0) { sc0 += z0[j + 2]; cc0 += 1.f; }
                    if (z0[j + 3] > tau0) { sd0 += z0[j + 3]; cd0 += 1.f; }
                    if (z1[j]     > tau1) { sa1 += z1[j];     ca1 += 1.f; }
                    if (z1[j + 1] > tau1) { sb1 += z1[j + 1]; cb1 += 1.f; }
                    if (z1[j + 2] > tau1) { sc1 += z1[j + 2]; cc1 += 1.f; }
                    if (z1[j + 3] > tau1) { sd1 += z1[j + 3]; cd1 += 1.f; }
                }
                float s0 = (sa0 + sb0) + (sc0 + sd0);
                float c0 = (ca0 + cb0) + (cc0 + cd0);
                float s1 = (sa1 + sb1) + (sc1 + sd1);
                float c1 = (ca1 + cb1) + (cc1 + cd1);
                s0 = warpSum(s0);
                c0 = warpSum(c0);
                s1 = warpSum(s1);
                c1 = warpSum(c1);
                const float nt0 = (s0 - 1.0f) / c0;
                const float nt1 = (s1 - 1.0f) / c1;
                const bool done = (nt0 == tau0) && (nt1 == tau1);
                tau0 = nt0;
                tau1 = nt1;
                if (done) break;
            }
#pragma unroll
            for (int j = 0; j < 32; ++j) {
                row0[j * 32 + lane] = to_tf32(fmaxf(z0[j] - tau0, 0.f));
                row1[j * 32 + lane] = to_tf32(fmaxf(z1[j] - tau1, 0.f));
            }
        } else {
            float s0 = 0.f, s1 = 0.f;
#pragma unroll
            for (int j = 0; j < 32; ++j) {
                z0[j] = __expf(z0[j] - mx0); s0 += z0[j];
                z1[j] = __expf(z1[j] - mx1); s1 += z1[j];
            }
            s0 = warpSum(s0);
            s1 = warpSum(s1);
            const float i0 = 1.0f / s0, i1 = 1.0f / s1;
#pragma unroll
            for (int j = 0; j < 32; ++j) {
                row0[j * 32 + lane] = to_tf32(z0[j] * i0);
                row1[j * 32 + lane] = to_tf32(z1[j] * i1);
            }
        }
    }

    // ---- phase 3: out = weights @ V (hi only), 2 accumulator chains ----
    float o1[4] = {}, o2[4] = {};
    for (int kc = 0; kc < NCH; ++kc) {
        CP_WAIT(0);
        __syncthreads();
        if (kc + 1 < NCH) {
            stage_cp1(kvH[(kc + 1) & 1], Vh + (kc + 1) * CK, tid, SEQ);
            CP_COMMIT();
        }

        const float* bH = kvH[kc & 1];
#pragma unroll
        for (int kk = 0; kk < CK / 8; ++kk) {
            const float* ap = sc + (16 * wq + g) * SCP + kc * CK + 8 * kk + 2 * t;
            float2 fa0 = *(const float2*)(ap);
            float2 fa1 = *(const float2*)(ap + 8 * SCP);
            unsigned a[4] = { __float_as_uint(fa0.x), __float_as_uint(fa1.x),
                              __float_as_uint(fa0.y), __float_as_uint(fa1.y) };
            const int boff = (8 * wk + g) * APS + 8 * kk + 2 * t;
            float2 fbh = *(const float2*)(bH + boff);
            unsigned bhf[2] = { __float_as_uint(fbh.x), __float_as_uint(fbh.y) };
            mma_tf32((kk & 1) ? o2 : o1, a, bhf);
        }
    }

    // write [B, S, H*HD]
    {
        const int q = q0 + 16 * wq + g;
        float* p = out + (size_t)(b * SEQ + q) * DM + h * DH + 8 * wk + 2 * t;
        *(float2*)p = make_float2(o1[0] + o2[0], o1[1] + o2[1]);
        *(float2*)(p + 8 * DM) = make_float2(o1[2] + o2[2], o1[3] + o2[3]);
    }
}

// ---------------------------------------------------------------------------
extern "C" void kernel_launch(void* const* d_in, const int* in_sizes, int n_in,
                              void* d_out, int out_size) {
    const float* X    = (const float*)d_in[0];
    const float* Wq   = (const float*)d_in[1];
    const float* bq   = (const float*)d_in[2];
    const float* Wk   = (const float*)d_in[3];
    const float* bk   = (const float*)d_in[4];
    const float* Wv   = (const float*)d_in[5];
    const float* bv   = (const float*)d_in[6];
    const float* mask = (const float*)d_in[7];
    float* out = (float*)d_out;

    presplit_x<<<MROWS * DM / 4 / 256, 256>>>(X);
    presplit_wt<<<dim3(DM / 64, DM / 64, 3), 256>>>(Wq, Wk, Wv);

    cudaFuncSetAttribute(qkv_proj_tc, cudaFuncAttributeMaxDynamicSharedMemorySize,
                         PROJ_SMEM_BYTES);
    dim3 gp(DM / 128, MROWS / 128, 3);
    qkv_proj_tc<<<gp, 256, PROJ_SMEM_BYTES>>>(bq, bk, bv);

    cudaFuncSetAttribute(attn_tc, cudaFuncAttributeMaxDynamicSharedMemorySize,
                         ATTN_SMEM_FLOATS * (int)sizeof(float));
    dim3 ga(SEQ / TQ, NH, NB);
    attn_tc<<<ga, NT, ATTN_SMEM_FLOATS * sizeof(float)>>>(mask, out);
}

// round 16
// speedup vs baseline: 1.6755x; 1.1271x over previous
#include <cuda_runtime.h>
#include <cuda_bf16.h>
#include <cstdint>

// Problem constants
#define NB   4
#define SEQ  1024
#define NH   16
#define DH   64
#define DM   1024
#define MROWS (NB * SEQ)

// bf16 hi/lo pre-split GEMM inputs. X: [m][k]; W: TRANSPOSED [n][k]. Both with
// pair-permutation inside each 16-k block (pair p -> pos ((p&3)<<1)|(p>>2)).
__device__ __nv_bfloat16 g_xbh[MROWS * DM], g_xbl[MROWS * DM];
__device__ __nv_bfloat16 g_wbh[3 * DM * DM], g_wbl[3 * DM * DM];

// Q/K: bf16 hi/lo, [B,H,S,DH], 16-block pair-permutation on DH (for k16 frags).
// V:   fp32 tf32-hi only, [B,H,DH,S] transposed, 8-block perm8 on s (tf32 k8).
__device__ __nv_bfloat16 g_qbh[NB * NH * SEQ * DH], g_qbl[NB * NH * SEQ * DH];
__device__ __nv_bfloat16 g_kbh[NB * NH * SEQ * DH], g_kbl[NB * NH * SEQ * DH];
__device__ float g_vh[NB * NH * SEQ * DH];

__device__ __forceinline__ int perm8(int x) { return ((x & 3) << 1) | ((x >> 2) & 1); }

__device__ __forceinline__ float to_tf32(float x) {
    unsigned u;
    asm("cvt.rna.tf32.f32 %0, %1;" : "=r"(u) : "f"(x));
    return __uint_as_float(u);
}
__device__ __forceinline__ void split_bf16(float x, __nv_bfloat16& hi, __nv_bfloat16& lo) {
    hi = __float2bfloat16(x);
    lo = __float2bfloat16(x - __bfloat162float(hi));
}
__device__ __forceinline__ void mma_tf32(float* c, const unsigned* a, const unsigned* b) {
    asm volatile(
        "mma.sync.aligned.m16n8k8.row.col.f32.tf32.tf32.f32 "
        "{%0,%1,%2,%3},{%4,%5,%6,%7},{%8,%9},{%0,%1,%2,%3};"
        : "+f"(c[0]), "+f"(c[1]), "+f"(c[2]), "+f"(c[3])
        : "r"(a[0]), "r"(a[1]), "r"(a[2]), "r"(a[3]), "r"(b[0]), "r"(b[1]));
}
__device__ __forceinline__ void mma_bf16(float* c, const unsigned* a, const unsigned* b) {
    asm volatile(
        "mma.sync.aligned.m16n8k16.row.col.f32.bf16.bf16.f32 "
        "{%0,%1,%2,%3},{%4,%5,%6,%7},{%8,%9},{%0,%1,%2,%3};"
        : "+f"(c[0]), "+f"(c[1]), "+f"(c[2]), "+f"(c[3])
        : "r"(a[0]), "r"(a[1]), "r"(a[2]), "r"(a[3]), "r"(b[0]), "r"(b[1]));
}
__device__ __forceinline__ float warpMax(float v) {
#pragma unroll
    for (int o = 16; o > 0; o >>= 1) v = fmaxf(v, __shfl_xor_sync(0xffffffffu, v, o));
    return v;
}
__device__ __forceinline__ float warpSum(float v) {
#pragma unroll
    for (int o = 16; o > 0; o >>= 1) v += __shfl_xor_sync(0xffffffffu, v, o);
    return v;
}

#define CP_COMMIT() asm volatile("cp.async.commit_group;")
#define CP_WAIT(N)  asm volatile("cp.async.wait_group %0;" :: "n"(N))

__device__ __forceinline__ void cp16(void* dst, const void* src) {
    uint32_t a = (uint32_t)__cvta_generic_to_shared(dst);
    asm volatile("cp.async.cg.shared.global [%0], [%1], 16;" :: "r"(a), "l"(src));
}

// ---------------------------------------------------------------------------
// Presplit X -> bf16 hi/lo [m][k], pair-permuted per 16-k block.
// ---------------------------------------------------------------------------
__global__ __launch_bounds__(256) void presplit_x(const float* __restrict__ X) {
    const int idx = blockIdx.x * 256 + threadIdx.x;
    const int row = idx >> 8;
    const int k4 = (idx & 255) << 2;
    float4 v = ((const float4*)X)[idx];
    const int kb = k4 & ~15;
    const int p0 = (k4 & 15) >> 1;
    const int p1 = p0 + 1;
    const int q0 = ((p0 & 3) << 1) | (p0 >> 2);
    const int q1 = ((p1 & 3) << 1) | (p1 >> 2);
    __nv_bfloat16 hx, lx, hy, ly, hz, lz, hw, lw;
    split_bf16(v.x, hx, lx); split_bf16(v.y, hy, ly);
    split_bf16(v.z, hz, lz); split_bf16(v.w, hw, lw);
    __nv_bfloat162* dh = (__nv_bfloat162*)(g_xbh + (size_t)row * DM + kb);
    __nv_bfloat162* dl = (__nv_bfloat162*)(g_xbl + (size_t)row * DM + kb);
    dh[q0] = __nv_bfloat162(hx, hy);
    dl[q0] = __nv_bfloat162(lx, ly);
    dh[q1] = __nv_bfloat162(hz, hw);
    dl[q1] = __nv_bfloat162(lz, lw);
}

// ---------------------------------------------------------------------------
// Presplit + TRANSPOSE W -> bf16 hi/lo [n][k], pair-permuted. smem-tiled 64x64.
// ---------------------------------------------------------------------------
__global__ __launch_bounds__(256) void presplit_wt(
    const float* __restrict__ Wq, const float* __restrict__ Wk,
    const float* __restrict__ Wv) {
    __shared__ __nv_bfloat16 sh[64 * 80], sl[64 * 80];
    const int z = blockIdx.z;
    const float* W = (z == 0) ? Wq : (z == 1) ? Wk : Wv;
    const size_t zo = (size_t)z * DM * DM;
    const int k0 = blockIdx.x * 64, n0 = blockIdx.y * 64;
    const int tid = threadIdx.x;
#pragma unroll
    for (int it = 0; it < 16; ++it) {
        const int e = tid + 256 * it;
        const int kk = e >> 6, nn = e & 63;
        float x = W[(size_t)(k0 + kk) * DM + n0 + nn];
        __nv_bfloat16 hi, lo;
        split_bf16(x, hi, lo);
        const int b16 = kk & ~15;
        const int p = (kk & 15) >> 1;
        const int q = ((p & 3) << 1) | (p >> 2);
        const int skk = b16 + (q << 1) + (kk & 1);
        sh[nn * 80 + skk] = hi;
        sl[nn * 80 + skk] = lo;
    }
    __syncthreads();
#pragma unroll
    for (int it = 0; it < 2; ++it) {
        const int e = tid + 256 * it;
        const int rr = e >> 3, cc = e & 7;
        *(uint4*)(g_wbh + zo + (size_t)(n0 + rr) * DM + k0 + cc * 8) =
            *(const uint4*)(sh + rr * 80 + cc * 8);
        *(uint4*)(g_wbl + zo + (size_t)(n0 + rr) * DM + k0 + cc * 8) =
            *(const uint4*)(sl + rr * 80 + cc * 8);
    }
}

// ---------------------------------------------------------------------------
// QKV projection, 3xBF16 m16n8k16 (R15-proven mainloop). 256 threads, 8 warps,
// CTA 128x128, k-stage 32 double-buffered (96 KB), 2 CTAs/SM.
// Epilogue: Q/K -> bf16 hi/lo (16-block pair-perm); V -> tf32-hi transposed.
// ---------------------------------------------------------------------------
constexpr int BST  = 48;
constexpr int BXS  = 128 * BST;
constexpr int BSTG = 4 * BXS;
constexpr int PROJ_SMEM_BYTES = 2 * BSTG * 2;

__device__ __forceinline__ void pstage(__nv_bfloat16* s,
                                       const __nv_bfloat16* xh, const __nv_bfloat16* xl,
                                       const __nv_bfloat16* wh, const __nv_bfloat16* wl,
                                       int m0, int n0, int k0, int tid) {
    __nv_bfloat16* Xh = s;
    __nv_bfloat16* Xl = s + BXS;
    __nv_bfloat16* Wh = s + 2 * BXS;
    __nv_bfloat16* Wl = s + 3 * BXS;
#pragma unroll
    for (int it = 0; it < 2; ++it) {
        const int idx = tid + 256 * it;
        const int r = idx >> 2, c = (idx & 3) << 3;
        const size_t gx = (size_t)(m0 + r) * DM + k0 + c;
        cp16(Xh + r * BST + c, xh + gx);
        cp16(Xl + r * BST + c, xl + gx);
        const size_t gw = (size_t)(n0 + r) * DM + k0 + c;
        cp16(Wh + r * BST + c, wh + gw);
        cp16(Wl + r * BST + c, wl + gw);
    }
}

__global__ __launch_bounds__(256, 2) void qkv_proj_tc(
    const float* __restrict__ bq, const float* __restrict__ bk,
    const float* __restrict__ bv) {
    extern __shared__ __nv_bfloat16 bsm[];

    const int z = blockIdx.z;
    const __nv_bfloat16* wbh = g_wbh + (size_t)z * DM * DM;
    const __nv_bfloat16* wbl = g_wbl + (size_t)z * DM * DM;
    const float* bias = (z == 0) ? bq : (z == 1) ? bk : bv;
    __nv_bfloat16* outbh = (z == 0) ? g_qbh : g_kbh;
    __nv_bfloat16* outbl = (z == 0) ? g_qbl : g_kbl;
    const bool isV = (z == 2);

    const int tid = threadIdx.x;
    const int warp = tid >> 5, lane = tid & 31;
    const int g = lane >> 2, t = lane & 3;
    const int wm = (warp >> 2) * 64, wn = (warp & 3) * 32;
    const int m0 = blockIdx.y * 128, n0 = blockIdx.x * 128;

    float acc[4][4][4] = {};

    pstage(bsm, g_xbh, g_xbl, wbh, wbl, m0, n0, 0, tid);
    CP_COMMIT();

    for (int kb = 0; kb < DM / 32; ++kb) {
        CP_WAIT(0);
        __syncthreads();
        if (kb + 1 < DM / 32) {
            pstage(bsm + ((kb + 1) & 1) * BSTG, g_xbh, g_xbl, wbh, wbl,
                   m0, n0, (kb + 1) * 32, tid);
            CP_COMMIT();
        }
        const __nv_bfloat16* Xh = bsm + (kb & 1) * BSTG;
        const __nv_bfloat16* Xl = Xh + BXS;
        const __nv_bfloat16* Wh = Xh + 2 * BXS;
        const __nv_bfloat16* Wl = Xh + 3 * BXS;

#pragma unroll
        for (int ks = 0; ks < 2; ++ks) {
            unsigned ah[4][4], al[4][4], bh[4][2], bl[4][2];
#pragma unroll
            for (int i = 0; i < 4; ++i) {
                const int base = (wm + 16 * i + g) * BST + ks * 16 + 4 * t;
                uint2 u0 = *(const uint2*)(Xh + base);
                uint2 u1 = *(const uint2*)(Xh + base + 8 * BST);
                ah[i][0] = u0.x; ah[i][1] = u1.x; ah[i][2] = u0.y; ah[i][3] = u1.y;
                uint2 e0 = *(const uint2*)(Xl + base);
                uint2 e1 = *(const uint2*)(Xl + base + 8 * BST);
                al[i][0] = e0.x; al[i][1] = e1.x; al[i][2] = e0.y; al[i][3] = e1.y;
            }
#pragma unroll
            for (int j = 0; j < 4; ++j) {
                const int base = (wn + 8 * j + g) * BST + ks * 16 + 4 * t;
                uint2 u = *(const uint2*)(Wh + base);
                bh[j][0] = u.x; bh[j][1] = u.y;
                uint2 e = *(const uint2*)(Wl + base);
                bl[j][0] = e.x; bl[j][1] = e.y;
            }
#pragma unroll
            for (int i = 0; i < 4; ++i)
#pragma unroll
                for (int j = 0; j < 4; ++j)
                    mma_bf16(acc[i][j], ah[i], bh[j]);
#pragma unroll
            for (int i = 0; i < 4; ++i)
#pragma unroll
                for (int j = 0; j < 4; ++j)
                    mma_bf16(acc[i][j], al[i], bh[j]);
#pragma unroll
            for (int i = 0; i < 4; ++i)
#pragma unroll
                for (int j = 0; j < 4; ++j)
                    mma_bf16(acc[i][j], ah[i], bl[j]);
        }
    }

    // epilogue: + bias, split, scatter
#pragma unroll
    for (int j = 0; j < 4; ++j) {
        const int n = n0 + wn + 8 * j + 2 * t;
        const float b0v = bias[n], b1v = bias[n + 1];
        const int h = n >> 6, hd = n & 63;
        // Q/K: 16-block pair-permuted bf16 position (hd even, hd+1 adjacent)
        const int pp = (hd & 15) >> 1;
        const int pos16 = (hd & ~15) + ((((pp & 3) << 1) | (pp >> 2)) << 1);
#pragma unroll
        for (int i = 0; i < 4; ++i) {
            const int m = m0 + wm + 16 * i + g;
            const int bI = m >> 10, s = m & 1023;
            const int m2 = m + 8;
            const int bI2 = m2 >> 10, s2 = m2 & 1023;
            const float v0 = acc[i][j][0] + b0v;
            const float v1 = acc[i][j][1] + b1v;
            const float v2 = acc[i][j][2] + b0v;
            const float v3 = acc[i][j][3] + b1v;
            if (!isV) {
                __nv_bfloat16 h0, l0, h1, l1;
                split_bf16(v0, h0, l0);
                split_bf16(v1, h1, l1);
                const size_t b1o = ((size_t)((bI * NH + h) * SEQ + s)) * DH;
                *(__nv_bfloat162*)(outbh + b1o + pos16) = __nv_bfloat162(h0, h1);
                *(__nv_bfloat162*)(outbl + b1o + pos16) = __nv_bfloat162(l0, l1);
                split_bf16(v2, h0, l0);
                split_bf16(v3, h1, l1);
                const size_t b2o = ((size_t)((bI2 * NH + h) * SEQ + s2)) * DH;
                *(__nv_bfloat162*)(outbh + b2o + pos16) = __nv_bfloat162(h0, h1);
                *(__nv_bfloat162*)(outbl + b2o + pos16) = __nv_bfloat162(l0, l1);
            } else {
                const int ps1 = (s & ~7) | perm8(s & 7);
                const int ps2 = (s2 & ~7) | perm8(s2 & 7);
                const size_t r0 = ((size_t)((bI * NH + h) * DH + hd)) * SEQ;
                const size_t r1 = ((size_t)((bI * NH + h) * DH + hd + 1)) * SEQ;
                g_vh[r0 + ps1] = to_tf32(v0);  g_vh[r1 + ps1] = to_tf32(v1);
                const size_t r0b = ((size_t)((bI2 * NH + h) * DH + hd)) * SEQ;
                const size_t r1b = ((size_t)((bI2 * NH + h) * DH + hd + 1)) * SEQ;
                g_vh[r0b + ps2] = to_tf32(v2);  g_vh[r1b + ps2] = to_tf32(v3);
            }
        }
    }
}

// ---------------------------------------------------------------------------
// Attention, 512 threads. Phase 1: bf16 m16n8k16 QK^T, K staged via cp.async
// double-buffer (stride 80 bf16, conflict-free), Q frags direct from GMEM.
// Phase 2: Michelot sparsemax / softmax (R12). Phase 3: tf32 w @ V-hi (R12).
// ---------------------------------------------------------------------------
constexpr int TQ  = 32;
constexpr int CK  = 64;
constexpr int NCH = SEQ / CK;     // 16
constexpr int NT  = 512;
constexpr int APS  = 72;          // V stage stride (floats)
constexpr int BKST = 80;          // K stage stride (bf16): banks (4g+t) unique
constexpr int KBSTG = CK * BKST;  // bf16 per K buffer (5120)
constexpr int SCP = 1032;
constexpr int KVSTG = CK * APS;   // floats per V buffer
constexpr int ATTN_SMEM_FLOATS = TQ * SCP + 4 * KVSTG;   // 201 KB
constexpr float SCALE = 0.125f;

__device__ __forceinline__ void stage_kbf(__nv_bfloat16* dh, __nv_bfloat16* dl,
                                          const __nv_bfloat16* gh,
                                          const __nv_bfloat16* gl, int tid) {
    const int r = tid >> 3, c = (tid & 7) << 3;    // 64 rows x 8 chunks of 8 bf16
    cp16(dh + r * BKST + c, gh + (size_t)r * DH + c);
    cp16(dl + r * BKST + c, gl + (size_t)r * DH + c);
}
__device__ __forceinline__ void stage_cp1(float* dh, const float* gh,
                                          int tid, int gstride) {
#pragma unroll
    for (int it = 0; it < 2; ++it) {
        const int idx = tid + 512 * it;
        const int r = idx >> 4, c = (idx & 15) << 2;
        cp16(dh + r * APS + c, gh + (size_t)r * gstride + c);
    }
}

__global__ __launch_bounds__(NT, 1) void attn_tc(const float* __restrict__ mask,
                                                 float* __restrict__ out) {
    extern __shared__ float sm[];
    float* sc = sm;                     // [TQ][SCP]
    float* kv = sm + TQ * SCP;          // union: bf16 K stages / fp32 V stages

    __nv_bfloat16* kb = (__nv_bfloat16*)kv;
    __nv_bfloat16* kbH[2] = { kb, kb + 2 * KBSTG };
    __nv_bfloat16* kbL[2] = { kb + KBSTG, kb + 3 * KBSTG };
    float* kvH[2] = { kv, kv + 2 * KVSTG };

    const int tid = threadIdx.x;
    const int b = blockIdx.z, h = blockIdx.y;
    const int q0 = blockIdx.x * TQ;
    const int bh_i = b * NH + h;
    const __nv_bfloat16* Qbh = g_qbh + ((size_t)bh_i * SEQ + q0) * DH;
    const __nv_bfloat16* Qbl = g_qbl + ((size_t)bh_i * SEQ + q0) * DH;
    const __nv_bfloat16* Kbh = g_kbh + (size_t)bh_i * SEQ * DH;
    const __nv_bfloat16* Kbl = g_kbl + (size_t)bh_i * SEQ * DH;
    const float* Vh = g_vh + (size_t)bh_i * DH * SEQ;
    const float* mrow = mask + b * SEQ;

    const int warp = tid >> 5, lane = tid & 31;
    const int g = lane >> 2, t = lane & 3;
    const int wq = warp >> 3;
    const int wk = warp & 7;

    stage_kbf(kbH[0], kbL[0], Kbh, Kbl, tid);
    CP_COMMIT();

    // Q fragments direct from GMEM (one-time, 32 regs)
    unsigned qah[4][4], qal[4][4];
    {
        const __nv_bfloat16* r0h = Qbh + (size_t)(16 * wq + g) * DH + 4 * t;
        const __nv_bfloat16* r1h = r0h + 8 * DH;
        const __nv_bfloat16* r0l = Qbl + (size_t)(16 * wq + g) * DH + 4 * t;
        const __nv_bfloat16* r1l = r0l + 8 * DH;
#pragma unroll
        for (int ks = 0; ks < 4; ++ks) {
            uint2 u0 = *(const uint2*)(r0h + 16 * ks);
            uint2 u1 = *(const uint2*)(r1h + 16 * ks);
            qah[ks][0] = u0.x; qah[ks][1] = u1.x; qah[ks][2] = u0.y; qah[ks][3] = u1.y;
            uint2 e0 = *(const uint2*)(r0l + 16 * ks);
            uint2 e1 = *(const uint2*)(r1l + 16 * ks);
            qal[ks][0] = e0.x; qal[ks][1] = e1.x; qal[ks][2] = e0.y; qal[ks][3] = e1.y;
        }
    }

    const int p0 = perm8(2 * t);

    // ---- phase 1: scores (bf16 k16, 12 MMAs/chunk) ----
    for (int kc = 0; kc < NCH; ++kc) {
        CP_WAIT(0);
        __syncthreads();
        if (kc + 1 < NCH) {
            stage_kbf(kbH[(kc + 1) & 1], kbL[(kc + 1) & 1],
                      Kbh + (size_t)(kc + 1) * CK * DH,
                      Kbl + (size_t)(kc + 1) * CK * DH, tid);
            CP_COMMIT();
        }

        const __nv_bfloat16* bH = kbH[kc & 1];
        const __nv_bfloat16* bL = kbL[kc & 1];
        float a1[4] = {}, a2[4] = {}, a3[4] = {};
#pragma unroll
        for (int ks = 0; ks < 4; ++ks) {
            const int boff = (8 * wk + g) * BKST + 16 * ks + 4 * t;
            uint2 u = *(const uint2*)(bH + boff);
            uint2 e = *(const uint2*)(bL + boff);
            unsigned bhf[2] = { u.x, u.y };
            unsigned blf[2] = { e.x, e.y };
            mma_bf16(a1, qah[ks], bhf);
            mma_bf16(a2, qal[ks], bhf);
            mma_bf16(a3, qah[ks], blf);
        }
        {
            const int bs = kc * CK + 8 * wk;
            const float2 mv = *(const float2*)(mrow + bs + 2 * t);
            const int q = 16 * wq + g;
            float c0 = a1[0] + a2[0] + a3[0];
            float c1 = a1[1] + a2[1] + a3[1];
            float c2 = a1[2] + a2[2] + a3[2];
            float c3 = a1[3] + a2[3] + a3[3];
            sc[q * SCP + bs + p0]           = fmaxf(fmaf(c0, SCALE, mv.x), -10000.0f);
            sc[q * SCP + bs + p0 + 2]       = fmaxf(fmaf(c1, SCALE, mv.y), -10000.0f);
            sc[(q + 8) * SCP + bs + p0]     = fmaxf(fmaf(c2, SCALE, mv.x), -10000.0f);
            sc[(q + 8) * SCP + bs + p0 + 2] = fmaxf(fmaf(c3, SCALE, mv.y), -10000.0f);
        }
    }

    stage_cp1(kvH[0], Vh, tid, SEQ);
    CP_COMMIT();
    __syncthreads();

    // ---- phase 2: Michelot sparsemax / softmax, 2 rows per warp ----
    {
        const bool sparse = ((h & 1) == 0);
        float* row0 = sc + warp * SCP;
        float* row1 = sc + (warp + 16) * SCP;
        float z0[32], z1[32];
#pragma unroll
        for (int j = 0; j < 32; ++j) { z0[j] = row0[j * 32 + lane]; z1[j] = row1[j * 32 + lane]; }
        float mx0 = -1e30f, mx1 = -1e30f;
#pragma unroll
        for (int j = 0; j < 32; ++j) { mx0 = fmaxf(mx0, z0[j]); mx1 = fmaxf(mx1, z1[j]); }
        mx0 = warpMax(mx0);
        mx1 = warpMax(mx1);

        if (sparse) {
            float tau0 = mx0 - 1.0f, tau1 = mx1 - 1.0f;
            for (int it = 0; it < 24; ++it) {
                float sa0 = 0.f, sb0 = 0.f, sc0 = 0.f, sd0 = 0.f;
                float ca0 = 0.f, cb0 = 0.f, cc0 = 0.f, cd0 = 0.f;
                float sa1 = 0.f, sb1 = 0.f, sc1 = 0.f, sd1 = 0.f;
                float ca1 = 0.f, cb1 = 0.f, cc1 = 0.f, cd1 = 0.f;
#pragma unroll
                for (int j = 0; j < 32; j += 4) {
                    if (z0[j]     > tau0) { sa0 += z0[j];     ca0 += 1.f; }
                    if (z0[j + 1] > tau0) { sb0 += z0[j + 1]; cb0 += 1.f; }
                    if (z0[j + 2] > tau0) { sc0 += z0[j + 2]; cc0 += 1.f; }
                    if (z0[j + 3] > tau0) { sd0 += z0[j + 3]; cd0 += 1.f; }
                    if (z1[j]     > tau1) { sa1 += z1[j];     ca1 += 1.f; }
                    if (z1[j + 1] > tau1) { sb1 += z1[j + 1]; cb1 += 1.f; }
                    if (z1[j + 2] > tau1) { sc1 += z1[j + 2]; cc1 += 1.f; }
                    if (z1[j + 3] > tau1) { sd1 += z1[j + 3]; cd1 += 1.f; }
                }
                float s0 = (sa0 + sb0) + (sc0 + sd0);
                float c0 = (ca0 + cb0) + (cc0 + cd0);
                float s1 = (sa1 + sb1) + (sc1 + sd1);
                float c1 = (ca1 + cb1) + (cc1 + cd1);
                s0 = warpSum(s0);
                c0 = warpSum(c0);
                s1 = warpSum(s1);
                c1 = warpSum(c1);
                const float nt0 = (s0 - 1.0f) / c0;
                const float nt1 = (s1 - 1.0f) / c1;
                const bool done = (nt0 == tau0) && (nt1 == tau1);
                tau0 = nt0;
                tau1 = nt1;
                if (done) break;
            }
#pragma unroll
            for (int j = 0; j < 32; ++j) {
                row0[j * 32 + lane] = to_tf32(fmaxf(z0[j] - tau0, 0.f));
                row1[j * 32 + lane] = to_tf32(fmaxf(z1[j] - tau1, 0.f));
            }
        } else {
            float s0 = 0.f, s1 = 0.f;
#pragma unroll
            for (int j = 0; j < 32; ++j) {
                z0[j] = __expf(z0[j] - mx0); s0 += z0[j];
                z1[j] = __expf(z1[j] - mx1); s1 += z1[j];
            }
            s0 = warpSum(s0);
            s1 = warpSum(s1);
            const float i0 = 1.0f / s0, i1 = 1.0f / s1;
#pragma unroll
            for (int j = 0; j < 32; ++j) {
                row0[j * 32 + lane] = to_tf32(z0[j] * i0);
                row1[j * 32 + lane] = to_tf32(z1[j] * i1);
            }
        }
    }

    // ---- phase 3: out = weights @ V (hi only), 2 accumulator chains ----
    float o1[4] = {}, o2[4] = {};
    for (int kc = 0; kc < NCH; ++kc) {
        CP_WAIT(0);
        __syncthreads();
        if (kc + 1 < NCH) {
            stage_cp1(kvH[(kc + 1) & 1], Vh + (kc + 1) * CK, tid, SEQ);
            CP_COMMIT();
        }

        const float* bH = kvH[kc & 1];
#pragma unroll
        for (int kk = 0; kk < CK / 8; ++kk) {
            const float* ap = sc + (16 * wq + g) * SCP + kc * CK + 8 * kk + 2 * t;
            float2 fa0 = *(const float2*)(ap);
            float2 fa1 = *(const float2*)(ap + 8 * SCP);
            unsigned a[4] = { __float_as_uint(fa0.x), __float_as_uint(fa1.x),
                              __float_as_uint(fa0.y), __float_as_uint(fa1.y) };
            const int boff = (8 * wk + g) * APS + 8 * kk + 2 * t;
            float2 fbh = *(const float2*)(bH + boff);
            unsigned bhf[2] = { __float_as_uint(fbh.x), __float_as_uint(fbh.y) };
            mma_tf32((kk & 1) ? o2 : o1, a, bhf);
        }
    }

    // write [B, S, H*HD]
    {
        const int q = q0 + 16 * wq + g;
        float* p = out + (size_t)(b * SEQ + q) * DM + h * DH + 8 * wk + 2 * t;
        *(float2*)p = make_float2(o1[0] + o2[0], o1[1] + o2[1]);
        *(float2*)(p + 8 * DM) = make_float2(o1[2] + o2[2], o1[3] + o2[3]);
    }
}

// ---------------------------------------------------------------------------
extern "C" void kernel_launch(void* const* d_in, const int* in_sizes, int n_in,
                              void* d_out, int out_size) {
    const float* X    = (const float*)d_in[0];
    const float* Wq   = (const float*)d_in[1];
    const float* bq   = (const float*)d_in[2];
    const float* Wk   = (const float*)d_in[3];
    const float* bk   = (const float*)d_in[4];
    const float* Wv   = (const float*)d_in[5];
    const float* bv   = (const float*)d_in[6];
    const float* mask = (const float*)d_in[7];
    float* out = (float*)d_out;

    presplit_x<<<MROWS * DM / 4 / 256, 256>>>(X);
    presplit_wt<<<dim3(DM / 64, DM / 64, 3), 256>>>(Wq, Wk, Wv);

    cudaFuncSetAttribute(qkv_proj_tc, cudaFuncAttributeMaxDynamicSharedMemorySize,
                         PROJ_SMEM_BYTES);
    dim3 gp(DM / 128, MROWS / 128, 3);
    qkv_proj_tc<<<gp, 256, PROJ_SMEM_BYTES>>>(bq, bk, bv);

    cudaFuncSetAttribute(attn_tc, cudaFuncAttributeMaxDynamicSharedMemorySize,
                         ATTN_SMEM_FLOATS * (int)sizeof(float));
    dim3 ga(SEQ / TQ, NH, NB);
    attn_tc<<<ga, NT, ATTN_SMEM_FLOATS * sizeof(float)>>>(mask, out);
}